// round 1
// baseline (speedup 1.0000x reference)
#include <cuda_runtime.h>
#include <cstdint>
#include <math.h>

// Problem constants
#define S_LEN 8192
#define DMODEL 1024
#define NHEAD 16
#define DHEAD 64
#define NSEG 8
#define SEG 1024

// Scratch (device globals; allocation-free per harness rules)
__device__ float g_qkv[S_LEN * 3 * DMODEL];   // [S, 3*D] : q | k | v per token
__device__ float g_attn[S_LEN * DMODEL];      // attention output [S, D]

// ---------------------------------------------------------------------------
// SGEMM (NT): C[m,n] = sum_k A[m,k]*B[n,k] + bias[n]
// BM=BN=128, BK=8, 256 threads, 8x8 per thread.
// ---------------------------------------------------------------------------
__global__ void __launch_bounds__(256) gemm_nt_bias(
    const float* __restrict__ A, const float* __restrict__ B,
    const float* __restrict__ bias, float* __restrict__ C,
    int M, int N, int K)
{
    __shared__ float As[8][128];
    __shared__ float Bs[8][128];

    const int t  = threadIdx.x;
    const int tx = t & 15;
    const int ty = t >> 4;
    const int m0 = blockIdx.y * 128;
    const int n0 = blockIdx.x * 128;

    const int lr = t >> 1;          // 0..127 row of tile
    const int lk = (t & 1) * 4;     // 0 or 4

    const float* Ap = A + (size_t)(m0 + lr) * K + lk;
    const float* Bp = B + (size_t)(n0 + lr) * K + lk;

    float acc[8][8];
#pragma unroll
    for (int i = 0; i < 8; i++)
#pragma unroll
        for (int j = 0; j < 8; j++) acc[i][j] = 0.0f;

    for (int k0 = 0; k0 < K; k0 += 8) {
        float4 a = *(const float4*)(Ap + k0);
        float4 b = *(const float4*)(Bp + k0);
        As[lk + 0][lr] = a.x; As[lk + 1][lr] = a.y;
        As[lk + 2][lr] = a.z; As[lk + 3][lr] = a.w;
        Bs[lk + 0][lr] = b.x; Bs[lk + 1][lr] = b.y;
        Bs[lk + 2][lr] = b.z; Bs[lk + 3][lr] = b.w;
        __syncthreads();

#pragma unroll
        for (int kk = 0; kk < 8; kk++) {
            float ra[8], rb[8];
            *(float4*)(ra)     = *(const float4*)&As[kk][ty * 8];
            *(float4*)(ra + 4) = *(const float4*)&As[kk][ty * 8 + 4];
            *(float4*)(rb)     = *(const float4*)&Bs[kk][tx * 8];
            *(float4*)(rb + 4) = *(const float4*)&Bs[kk][tx * 8 + 4];
#pragma unroll
            for (int i = 0; i < 8; i++)
#pragma unroll
                for (int j = 0; j < 8; j++)
                    acc[i][j] = fmaf(ra[i], rb[j], acc[i][j]);
        }
        __syncthreads();
    }

#pragma unroll
    for (int i = 0; i < 8; i++) {
        int m = m0 + ty * 8 + i;
#pragma unroll
        for (int j = 0; j < 8; j += 4) {
            int n = n0 + tx * 8 + j;
            float4 o;
            o.x = acc[i][j + 0] + bias[n + 0];
            o.y = acc[i][j + 1] + bias[n + 1];
            o.z = acc[i][j + 2] + bias[n + 2];
            o.w = acc[i][j + 3] + bias[n + 3];
            *(float4*)&C[(size_t)m * N + n] = o;
        }
    }
}

// ---------------------------------------------------------------------------
// RoPE in place on q and k halves of g_qkv.
// One thread per (token, which, head, d<32): handles the (d, d+32) pair.
// cos/sin tables are [S, 64].
// ---------------------------------------------------------------------------
__global__ void __launch_bounds__(256) rope_kernel(
    float* __restrict__ qkv,
    const float* __restrict__ cosT, const float* __restrict__ sinT)
{
    int idx = blockIdx.x * blockDim.x + threadIdx.x;
    // layout: d(5 bits) | h(4 bits) | w(1 bit) | s
    int d = idx & 31;
    int h = (idx >> 5) & 15;
    int w = (idx >> 9) & 1;
    int s = idx >> 10;
    if (s >= S_LEN) return;

    float* base = qkv + (size_t)s * (3 * DMODEL) + w * DMODEL + h * DHEAD;
    float x1 = base[d];
    float x2 = base[d + 32];
    float c1 = cosT[s * DHEAD + d];
    float s1 = sinT[s * DHEAD + d];
    float c2 = cosT[s * DHEAD + d + 32];
    float s2 = sinT[s * DHEAD + d + 32];
    base[d]      = x1 * c1 - x2 * s1;   // rotate_half: [-x2, x1]
    base[d + 32] = x2 * c2 + x1 * s2;
}

// ---------------------------------------------------------------------------
// Flash attention fp32.
// Block = (query tile of 64, head, segment). 256 threads = 16x16.
// Each thread: 4 query rows (ty*4..) x 4 cols.
// K-tile loop over 16 tiles of 64 keys, online softmax.
// SMEM (dynamic):
//   Qs [64k][68m]   transposed Q tile
//   Ks [64k][68j]   transposed K tile
//   Vs [64j][64d]   row-major V tile
//   Ps [64j][68m]   transposed P tile
// ---------------------------------------------------------------------------
#define QS_OFF 0
#define KS_OFF (64 * 68)
#define VS_OFF (KS_OFF + 64 * 68)
#define PS_OFF (VS_OFF + 64 * 64)
#define ATTN_SMEM_FLOATS (PS_OFF + 64 * 68)
#define ATTN_SMEM_BYTES (ATTN_SMEM_FLOATS * 4)

__global__ void __launch_bounds__(256) attn_kernel(
    const float* __restrict__ qkv, float* __restrict__ out)
{
    extern __shared__ float sm[];
    float* Qs = sm + QS_OFF;
    float* Ks = sm + KS_OFF;
    float* Vs = sm + VS_OFF;
    float* Ps = sm + PS_OFF;

    const int mt = blockIdx.x;      // 0..15 query tile
    const int h  = blockIdx.y;      // head
    const int sg = blockIdx.z;      // segment

    const int t  = threadIdx.x;
    const int tx = t & 15;
    const int ty = t >> 4;
    const int m0 = mt * 64;

    const float* qbase = qkv + (size_t)(sg * SEG) * (3 * DMODEL) + h * DHEAD;
    const float* kbase = qbase + DMODEL;
    const float* vbase = qbase + 2 * DMODEL;

    // Load Q tile transposed: Qs[k][m]
#pragma unroll
    for (int i = 0; i < 4; i++) {
        int f  = t + i * 256;          // float4 index 0..1023
        int r  = f >> 4;               // row within tile 0..63
        int kg = (f & 15) << 2;        // k offset 0,4,..,60
        float4 v = *(const float4*)(qbase + (size_t)(m0 + r) * (3 * DMODEL) + kg);
        Qs[(kg + 0) * 68 + r] = v.x;
        Qs[(kg + 1) * 68 + r] = v.y;
        Qs[(kg + 2) * 68 + r] = v.z;
        Qs[(kg + 3) * 68 + r] = v.w;
    }

    float acc[4][4];
    float mrow[4], lrow[4];
#pragma unroll
    for (int mm = 0; mm < 4; mm++) {
        mrow[mm] = -INFINITY;
        lrow[mm] = 0.0f;
#pragma unroll
        for (int dd = 0; dd < 4; dd++) acc[mm][dd] = 0.0f;
    }
    __syncthreads();

    for (int j0 = 0; j0 < SEG; j0 += 64) {
        // Load K (transposed) and V (row-major) tiles
#pragma unroll
        for (int i = 0; i < 4; i++) {
            int f  = t + i * 256;
            int r  = f >> 4;
            int kg = (f & 15) << 2;
            float4 kv = *(const float4*)(kbase + (size_t)(j0 + r) * (3 * DMODEL) + kg);
            Ks[(kg + 0) * 68 + r] = kv.x;
            Ks[(kg + 1) * 68 + r] = kv.y;
            Ks[(kg + 2) * 68 + r] = kv.z;
            Ks[(kg + 3) * 68 + r] = kv.w;
            float4 vv = *(const float4*)(vbase + (size_t)(j0 + r) * (3 * DMODEL) + kg);
            *(float4*)&Vs[r * 64 + kg] = vv;
        }
        __syncthreads();

        // S tile: s[mm][jj] = dot(Q[m0+ty*4+mm,:], K[j0+tx*4+jj,:])
        float s[4][4];
#pragma unroll
        for (int mm = 0; mm < 4; mm++)
#pragma unroll
            for (int jj = 0; jj < 4; jj++) s[mm][jj] = 0.0f;

#pragma unroll 8
        for (int kk = 0; kk < 64; kk++) {
            float4 q4 = *(const float4*)&Qs[kk * 68 + ty * 4];
            float4 k4 = *(const float4*)&Ks[kk * 68 + tx * 4];
            float qa[4] = {q4.x, q4.y, q4.z, q4.w};
            float ka[4] = {k4.x, k4.y, k4.z, k4.w};
#pragma unroll
            for (int mm = 0; mm < 4; mm++)
#pragma unroll
                for (int jj = 0; jj < 4; jj++)
                    s[mm][jj] = fmaf(qa[mm], ka[jj], s[mm][jj]);
        }

        // Online softmax per row (row spread over 16 tx lanes)
#pragma unroll
        for (int mm = 0; mm < 4; mm++) {
            float tm = -INFINITY;
#pragma unroll
            for (int jj = 0; jj < 4; jj++) {
                s[mm][jj] *= 0.125f;     // DH^-0.5
                tm = fmaxf(tm, s[mm][jj]);
            }
#pragma unroll
            for (int o = 8; o >= 1; o >>= 1)
                tm = fmaxf(tm, __shfl_xor_sync(0xffffffffu, tm, o));

            float mn  = fmaxf(mrow[mm], tm);
            float fac = __expf(mrow[mm] - mn);
            mrow[mm] = mn;

            float rs = 0.0f;
#pragma unroll
            for (int jj = 0; jj < 4; jj++) {
                s[mm][jj] = __expf(s[mm][jj] - mn);
                rs += s[mm][jj];
            }
#pragma unroll
            for (int o = 8; o >= 1; o >>= 1)
                rs += __shfl_xor_sync(0xffffffffu, rs, o);

            lrow[mm] = lrow[mm] * fac + rs;
#pragma unroll
            for (int dd = 0; dd < 4; dd++) acc[mm][dd] *= fac;
        }

        // Write P transposed: Ps[j][m]
#pragma unroll
        for (int mm = 0; mm < 4; mm++)
#pragma unroll
            for (int jj = 0; jj < 4; jj++)
                Ps[(tx * 4 + jj) * 68 + ty * 4 + mm] = s[mm][jj];
        __syncthreads();

        // acc += P @ V
#pragma unroll 8
        for (int j = 0; j < 64; j++) {
            float4 p4 = *(const float4*)&Ps[j * 68 + ty * 4];
            float4 v4 = *(const float4*)&Vs[j * 64 + tx * 4];
            float pa[4] = {p4.x, p4.y, p4.z, p4.w};
            float va[4] = {v4.x, v4.y, v4.z, v4.w};
#pragma unroll
            for (int mm = 0; mm < 4; mm++)
#pragma unroll
                for (int dd = 0; dd < 4; dd++)
                    acc[mm][dd] = fmaf(pa[mm], va[dd], acc[mm][dd]);
        }
        __syncthreads();   // before next tile overwrites Ks/Vs/Ps
    }

    // Epilogue: out[token, h*64 + d] = acc / l
#pragma unroll
    for (int mm = 0; mm < 4; mm++) {
        int tok = sg * SEG + m0 + ty * 4 + mm;
        float inv = 1.0f / lrow[mm];
        float4 o;
        o.x = acc[mm][0] * inv;
        o.y = acc[mm][1] * inv;
        o.z = acc[mm][2] * inv;
        o.w = acc[mm][3] * inv;
        *(float4*)&out[(size_t)tok * DMODEL + h * DHEAD + tx * 4] = o;
    }
}

// ---------------------------------------------------------------------------
// Launch
// ---------------------------------------------------------------------------
extern "C" void kernel_launch(void* const* d_in, const int* in_sizes, int n_in,
                              void* d_out, int out_size)
{
    const float* hs     = (const float*)d_in[0];
    const float* cosT   = (const float*)d_in[1];
    const float* sinT   = (const float*)d_in[2];
    const float* qkv_w  = (const float*)d_in[3];
    const float* qkv_b  = (const float*)d_in[4];
    const float* proj_w = (const float*)d_in[5];
    const float* proj_b = (const float*)d_in[6];
    // d_in[7] = cu_seqlens (fixed equal segments; constants baked in)
    float* out = (float*)d_out;

    void *qkvp_v, *attnp_v;
    cudaGetSymbolAddress(&qkvp_v, g_qkv);
    cudaGetSymbolAddress(&attnp_v, g_attn);
    float* qkvp  = (float*)qkvp_v;
    float* attnp = (float*)attnp_v;

    cudaFuncSetAttribute(attn_kernel,
                         cudaFuncAttributeMaxDynamicSharedMemorySize,
                         ATTN_SMEM_BYTES);

    // 1) QKV GEMM: [8192,1024] @ [3072,1024]^T + bias -> g_qkv [8192,3072]
    {
        dim3 grid(3 * DMODEL / 128, S_LEN / 128);
        gemm_nt_bias<<<grid, 256>>>(hs, qkv_w, qkv_b, qkvp,
                                    S_LEN, 3 * DMODEL, DMODEL);
    }

    // 2) RoPE in place on q,k
    {
        int total = S_LEN * 2 * NHEAD * 32;   // 8,388,608
        rope_kernel<<<total / 256, 256>>>(qkvp, cosT, sinT);
    }

    // 3) Attention -> g_attn [8192,1024]
    {
        dim3 grid(SEG / 64, NHEAD, NSEG);
        attn_kernel<<<grid, 256, ATTN_SMEM_BYTES>>>(qkvp, attnp);
    }

    // 4) Output projection: g_attn @ proj_w^T + bias -> d_out
    {
        dim3 grid(DMODEL / 128, S_LEN / 128);
        gemm_nt_bias<<<grid, 256>>>(attnp, proj_w, proj_b, out,
                                    S_LEN, DMODEL, DMODEL);
    }
}

// round 3
// speedup vs baseline: 1.3274x; 1.3274x over previous
#include <cuda_runtime.h>
#include <cstdint>
#include <math.h>

// Problem constants
#define S_LEN 8192
#define DMODEL 1024
#define NHEAD 16
#define DHEAD 64
#define NSEG 8
#define SEG 1024

// Scratch (device globals; allocation-free per harness rules)
__device__ float g_qkv[S_LEN * 3 * DMODEL];   // [S, 3*D] : q | k | v per token
__device__ float g_attn[S_LEN * DMODEL];      // attention output [S, D]

// ---------------------------------------------------------------------------
// SGEMM (NT): C[m,n] = sum_k A[m,k]*B[n,k] + bias[n]   (fp32 exact)
// ---------------------------------------------------------------------------
__global__ void __launch_bounds__(256) gemm_nt_bias(
    const float* __restrict__ A, const float* __restrict__ B,
    const float* __restrict__ bias, float* __restrict__ C,
    int M, int N, int K)
{
    __shared__ float As[8][128];
    __shared__ float Bs[8][128];

    const int t  = threadIdx.x;
    const int tx = t & 15;
    const int ty = t >> 4;
    const int m0 = blockIdx.y * 128;
    const int n0 = blockIdx.x * 128;

    const int lr = t >> 1;
    const int lk = (t & 1) * 4;

    const float* Ap = A + (size_t)(m0 + lr) * K + lk;
    const float* Bp = B + (size_t)(n0 + lr) * K + lk;

    float acc[8][8];
#pragma unroll
    for (int i = 0; i < 8; i++)
#pragma unroll
        for (int j = 0; j < 8; j++) acc[i][j] = 0.0f;

    for (int k0 = 0; k0 < K; k0 += 8) {
        float4 a = *(const float4*)(Ap + k0);
        float4 b = *(const float4*)(Bp + k0);
        As[lk + 0][lr] = a.x; As[lk + 1][lr] = a.y;
        As[lk + 2][lr] = a.z; As[lk + 3][lr] = a.w;
        Bs[lk + 0][lr] = b.x; Bs[lk + 1][lr] = b.y;
        Bs[lk + 2][lr] = b.z; Bs[lk + 3][lr] = b.w;
        __syncthreads();

#pragma unroll
        for (int kk = 0; kk < 8; kk++) {
            float ra[8], rb[8];
            *(float4*)(ra)     = *(const float4*)&As[kk][ty * 8];
            *(float4*)(ra + 4) = *(const float4*)&As[kk][ty * 8 + 4];
            *(float4*)(rb)     = *(const float4*)&Bs[kk][tx * 8];
            *(float4*)(rb + 4) = *(const float4*)&Bs[kk][tx * 8 + 4];
#pragma unroll
            for (int i = 0; i < 8; i++)
#pragma unroll
                for (int j = 0; j < 8; j++)
                    acc[i][j] = fmaf(ra[i], rb[j], acc[i][j]);
        }
        __syncthreads();
    }

#pragma unroll
    for (int i = 0; i < 8; i++) {
        int m = m0 + ty * 8 + i;
#pragma unroll
        for (int j = 0; j < 8; j += 4) {
            int n = n0 + tx * 8 + j;
            float4 o;
            o.x = acc[i][j + 0] + bias[n + 0];
            o.y = acc[i][j + 1] + bias[n + 1];
            o.z = acc[i][j + 2] + bias[n + 2];
            o.w = acc[i][j + 3] + bias[n + 3];
            *(float4*)&C[(size_t)m * N + n] = o;
        }
    }
}

// ---------------------------------------------------------------------------
// TF32 helpers
// ---------------------------------------------------------------------------
__device__ __forceinline__ unsigned f2tf(float x) {
    unsigned u;
    asm("cvt.rna.tf32.f32 %0, %1;" : "=r"(u) : "f"(x));
    return u;
}
__device__ __forceinline__ float f2tff(float x) { return __uint_as_float(f2tf(x)); }

__device__ __forceinline__ void mma_tf32(
    float c[4], unsigned a0, unsigned a1, unsigned a2, unsigned a3,
    unsigned b0, unsigned b1)
{
    asm volatile(
        "mma.sync.aligned.m16n8k8.row.col.f32.tf32.tf32.f32 "
        "{%0,%1,%2,%3},{%4,%5,%6,%7},{%8,%9},{%0,%1,%2,%3};"
        : "+f"(c[0]), "+f"(c[1]), "+f"(c[2]), "+f"(c[3])
        : "r"(a0), "r"(a1), "r"(a2), "r"(a3), "r"(b0), "r"(b1));
}

// ---------------------------------------------------------------------------
// Tensor-core flash attention (tf32 mma, fp32 accumulate), RoPE fused into
// the Q/K tile loads.
// Block: 256 threads = 8 warps; Q tile = 128 rows; each warp owns m16 rows.
// K tiles of 64 keys. smem: Ks[64][68], Vs[64][72]; Qs[128][68] prologue
// overlay of the same region.
// ---------------------------------------------------------------------------
#define KS_STRIDE 68
#define VS_STRIDE 72

__global__ void __launch_bounds__(256) attn_tc_kernel(
    const float* __restrict__ qkv, float* __restrict__ out,
    const float* __restrict__ cosT, const float* __restrict__ sinT)
{
    __shared__ float sm[64 * KS_STRIDE + 64 * VS_STRIDE];  // 8960 floats
    float* Ks = sm;
    float* Vs = sm + 64 * KS_STRIDE;
    float* Qs = sm;  // prologue-only overlay, stride 68, 128 rows (8704 f)

    const int mt = blockIdx.x;   // q tile within segment (0..7)
    const int h  = blockIdx.y;
    const int sg = blockIdx.z;

    const int t    = threadIdx.x;
    const int lane = t & 31;
    const int warp = t >> 5;
    const int g    = lane >> 2;   // groupID (row within fragment)
    const int tg   = lane & 3;    // threadID_in_group

    // ---- Prologue: load Q tile with RoPE + scale + tf32 round ----
#pragma unroll
    for (int i = 0; i < 4; i++) {
        int f  = t + i * 256;        // 0..1023
        int r  = f >> 3;             // row 0..127
        int c4 = (f & 7) * 4;        // 0..28 (low half)
        int tok = sg * SEG + mt * 128 + r;
        const float* src = qkv + (size_t)tok * (3 * DMODEL) + h * DHEAD;
        float4 x1 = *(const float4*)(src + c4);
        float4 x2 = *(const float4*)(src + c4 + 32);
        float4 c1 = *(const float4*)(cosT + tok * DHEAD + c4);
        float4 s1 = *(const float4*)(sinT + tok * DHEAD + c4);
        float4 c2 = *(const float4*)(cosT + tok * DHEAD + c4 + 32);
        float4 s2 = *(const float4*)(sinT + tok * DHEAD + c4 + 32);
        float* d1 = &Qs[r * KS_STRIDE + c4];
        float* d2 = d1 + 32;
        d1[0] = f2tff((x1.x * c1.x - x2.x * s1.x) * 0.125f);
        d1[1] = f2tff((x1.y * c1.y - x2.y * s1.y) * 0.125f);
        d1[2] = f2tff((x1.z * c1.z - x2.z * s1.z) * 0.125f);
        d1[3] = f2tff((x1.w * c1.w - x2.w * s1.w) * 0.125f);
        d2[0] = f2tff((x2.x * c2.x + x1.x * s2.x) * 0.125f);
        d2[1] = f2tff((x2.y * c2.y + x1.y * s2.y) * 0.125f);
        d2[2] = f2tff((x2.z * c2.z + x1.z * s2.z) * 0.125f);
        d2[3] = f2tff((x2.w * c2.w + x1.w * s2.w) * 0.125f);
    }
    __syncthreads();

    // Extract Q A-fragments (m16 x k8 per step, 8 k-steps)
    unsigned qa[8][4];
    {
        int row = warp * 16 + g;
#pragma unroll
        for (int ks = 0; ks < 8; ks++) {
            int c = ks * 8 + tg;
            qa[ks][0] = __float_as_uint(Qs[row * KS_STRIDE + c]);
            qa[ks][1] = __float_as_uint(Qs[(row + 8) * KS_STRIDE + c]);
            qa[ks][2] = __float_as_uint(Qs[row * KS_STRIDE + c + 4]);
            qa[ks][3] = __float_as_uint(Qs[(row + 8) * KS_STRIDE + c + 4]);
        }
    }
    __syncthreads();

    float acc[8][4];
#pragma unroll
    for (int nb = 0; nb < 8; nb++)
#pragma unroll
        for (int i = 0; i < 4; i++) acc[nb][i] = 0.0f;
    float m_lo = -INFINITY, m_hi = -INFINITY, l_lo = 0.0f, l_hi = 0.0f;

    const int srcA = (lane & ~3) | (tg >> 1);
    const int srcB = srcA | 2;
    const bool odd = lane & 1;

    for (int j0 = 0; j0 < SEG; j0 += 64) {
        // ---- Load K tile with RoPE (512 pair-tasks) ----
#pragma unroll
        for (int i = 0; i < 2; i++) {
            int f  = t + i * 256;     // 0..511
            int r  = f >> 3;          // row 0..63
            int c4 = (f & 7) * 4;
            int tok = sg * SEG + j0 + r;
            const float* src = qkv + (size_t)tok * (3 * DMODEL) + DMODEL + h * DHEAD;
            float4 x1 = *(const float4*)(src + c4);
            float4 x2 = *(const float4*)(src + c4 + 32);
            float4 c1 = *(const float4*)(cosT + tok * DHEAD + c4);
            float4 s1 = *(const float4*)(sinT + tok * DHEAD + c4);
            float4 c2 = *(const float4*)(cosT + tok * DHEAD + c4 + 32);
            float4 s2 = *(const float4*)(sinT + tok * DHEAD + c4 + 32);
            float* d1 = &Ks[r * KS_STRIDE + c4];
            float* d2 = d1 + 32;
            d1[0] = f2tff(x1.x * c1.x - x2.x * s1.x);
            d1[1] = f2tff(x1.y * c1.y - x2.y * s1.y);
            d1[2] = f2tff(x1.z * c1.z - x2.z * s1.z);
            d1[3] = f2tff(x1.w * c1.w - x2.w * s1.w);
            d2[0] = f2tff(x2.x * c2.x + x1.x * s2.x);
            d2[1] = f2tff(x2.y * c2.y + x1.y * s2.y);
            d2[2] = f2tff(x2.z * c2.z + x1.z * s2.z);
            d2[3] = f2tff(x2.w * c2.w + x1.w * s2.w);
        }
        // ---- Load V tile (tf32 round, no rope) ----
#pragma unroll
        for (int i = 0; i < 4; i++) {
            int f  = t + i * 256;
            int r  = f >> 4;          // 0..63
            int c4 = (f & 15) * 4;
            int tok = sg * SEG + j0 + r;
            float4 vv = *(const float4*)(qkv + (size_t)tok * (3 * DMODEL) + 2 * DMODEL + h * DHEAD + c4);
            float* d = &Vs[r * VS_STRIDE + c4];
            d[0] = f2tff(vv.x);
            d[1] = f2tff(vv.y);
            d[2] = f2tff(vv.z);
            d[3] = f2tff(vv.w);
        }
        __syncthreads();

        // ---- S = Q K^T (16 x 64 per warp) ----
        float sf[8][4];
#pragma unroll
        for (int nb = 0; nb < 8; nb++) {
            sf[nb][0] = sf[nb][1] = sf[nb][2] = sf[nb][3] = 0.0f;
            const float* kp = &Ks[(nb * 8 + g) * KS_STRIDE + tg];
#pragma unroll
            for (int ks = 0; ks < 8; ks++) {
                unsigned b0 = __float_as_uint(kp[ks * 8]);
                unsigned b1 = __float_as_uint(kp[ks * 8 + 4]);
                mma_tf32(sf[nb], qa[ks][0], qa[ks][1], qa[ks][2], qa[ks][3], b0, b1);
            }
        }

        // ---- Online softmax (rows: lo = g, hi = g+8 within warp's 16) ----
        float tmax_lo = -INFINITY, tmax_hi = -INFINITY;
#pragma unroll
        for (int nb = 0; nb < 8; nb++) {
            tmax_lo = fmaxf(tmax_lo, fmaxf(sf[nb][0], sf[nb][1]));
            tmax_hi = fmaxf(tmax_hi, fmaxf(sf[nb][2], sf[nb][3]));
        }
        tmax_lo = fmaxf(tmax_lo, __shfl_xor_sync(0xffffffffu, tmax_lo, 1));
        tmax_lo = fmaxf(tmax_lo, __shfl_xor_sync(0xffffffffu, tmax_lo, 2));
        tmax_hi = fmaxf(tmax_hi, __shfl_xor_sync(0xffffffffu, tmax_hi, 1));
        tmax_hi = fmaxf(tmax_hi, __shfl_xor_sync(0xffffffffu, tmax_hi, 2));

        float mn_lo = fmaxf(m_lo, tmax_lo);
        float mn_hi = fmaxf(m_hi, tmax_hi);
        float fac_lo = __expf(m_lo - mn_lo);
        float fac_hi = __expf(m_hi - mn_hi);
        m_lo = mn_lo; m_hi = mn_hi;

        float rs_lo = 0.0f, rs_hi = 0.0f;
#pragma unroll
        for (int nb = 0; nb < 8; nb++) {
            sf[nb][0] = __expf(sf[nb][0] - m_lo);
            sf[nb][1] = __expf(sf[nb][1] - m_lo);
            sf[nb][2] = __expf(sf[nb][2] - m_hi);
            sf[nb][3] = __expf(sf[nb][3] - m_hi);
            rs_lo += sf[nb][0] + sf[nb][1];
            rs_hi += sf[nb][2] + sf[nb][3];
        }
        rs_lo += __shfl_xor_sync(0xffffffffu, rs_lo, 1);
        rs_lo += __shfl_xor_sync(0xffffffffu, rs_lo, 2);
        rs_hi += __shfl_xor_sync(0xffffffffu, rs_hi, 1);
        rs_hi += __shfl_xor_sync(0xffffffffu, rs_hi, 2);

        l_lo = l_lo * fac_lo + rs_lo;
        l_hi = l_hi * fac_hi + rs_hi;
#pragma unroll
        for (int nb = 0; nb < 8; nb++) {
            acc[nb][0] *= fac_lo; acc[nb][1] *= fac_lo;
            acc[nb][2] *= fac_hi; acc[nb][3] *= fac_hi;
        }

        // ---- acc += P V : convert P C-frags -> A-frags via shuffles ----
#pragma unroll
        for (int kc = 0; kc < 8; kc++) {
            float x0 = __shfl_sync(0xffffffffu, sf[kc][0], srcA);
            float x1 = __shfl_sync(0xffffffffu, sf[kc][1], srcA);
            float y0 = __shfl_sync(0xffffffffu, sf[kc][0], srcB);
            float y1 = __shfl_sync(0xffffffffu, sf[kc][1], srcB);
            float z0 = __shfl_sync(0xffffffffu, sf[kc][2], srcA);
            float z1 = __shfl_sync(0xffffffffu, sf[kc][3], srcA);
            float w0 = __shfl_sync(0xffffffffu, sf[kc][2], srcB);
            float w1 = __shfl_sync(0xffffffffu, sf[kc][3], srcB);
            unsigned pa0 = f2tf(odd ? x1 : x0);
            unsigned pa2 = f2tf(odd ? y1 : y0);
            unsigned pa1 = f2tf(odd ? z1 : z0);
            unsigned pa3 = f2tf(odd ? w1 : w0);

            const float* vp = &Vs[(kc * 8 + tg) * VS_STRIDE + g];
#pragma unroll
            for (int nb = 0; nb < 8; nb++) {
                unsigned vb0 = __float_as_uint(vp[nb * 8]);
                unsigned vb1 = __float_as_uint(vp[nb * 8 + 4 * VS_STRIDE]);
                mma_tf32(acc[nb], pa0, pa1, pa2, pa3, vb0, vb1);
            }
        }
        __syncthreads();
    }

    // ---- Epilogue ----
    float inv_lo = 1.0f / l_lo;
    float inv_hi = 1.0f / l_hi;
    int tok_lo = sg * SEG + mt * 128 + warp * 16 + g;
#pragma unroll
    for (int nb = 0; nb < 8; nb++) {
        int col = h * DHEAD + nb * 8 + tg * 2;
        float2 o;
        o.x = acc[nb][0] * inv_lo;
        o.y = acc[nb][1] * inv_lo;
        *(float2*)&out[(size_t)tok_lo * DMODEL + col] = o;
        o.x = acc[nb][2] * inv_hi;
        o.y = acc[nb][3] * inv_hi;
        *(float2*)&out[(size_t)(tok_lo + 8) * DMODEL + col] = o;
    }
}

// ---------------------------------------------------------------------------
// Launch
// ---------------------------------------------------------------------------
extern "C" void kernel_launch(void* const* d_in, const int* in_sizes, int n_in,
                              void* d_out, int out_size)
{
    const float* hs     = (const float*)d_in[0];
    const float* cosT   = (const float*)d_in[1];
    const float* sinT   = (const float*)d_in[2];
    const float* qkv_w  = (const float*)d_in[3];
    const float* qkv_b  = (const float*)d_in[4];
    const float* proj_w = (const float*)d_in[5];
    const float* proj_b = (const float*)d_in[6];
    float* out = (float*)d_out;

    void *qkvp_v, *attnp_v;
    cudaGetSymbolAddress(&qkvp_v, g_qkv);
    cudaGetSymbolAddress(&attnp_v, g_attn);
    float* qkvp  = (float*)qkvp_v;
    float* attnp = (float*)attnp_v;

    // 1) QKV GEMM (fp32 exact)
    {
        dim3 grid(3 * DMODEL / 128, S_LEN / 128);
        gemm_nt_bias<<<grid, 256>>>(hs, qkv_w, qkv_b, qkvp,
                                    S_LEN, 3 * DMODEL, DMODEL);
    }

    // 2) Attention (tf32 tensor cores, RoPE fused) -> g_attn
    {
        dim3 grid(SEG / 128, NHEAD, NSEG);
        attn_tc_kernel<<<grid, 256>>>(qkvp, attnp, cosT, sinT);
    }

    // 3) Output projection (fp32 exact)
    {
        dim3 grid(DMODEL / 128, S_LEN / 128);
        gemm_nt_bias<<<grid, 256>>>(attnp, proj_w, proj_b, out,
                                    S_LEN, DMODEL, DMODEL);
    }
}

// round 4
// speedup vs baseline: 1.4348x; 1.0809x over previous
#include <cuda_runtime.h>
#include <cuda_fp16.h>
#include <cstdint>
#include <math.h>

// Problem constants
#define S_LEN 8192
#define DMODEL 1024
#define NHEAD 16
#define DHEAD 64
#define NSEG 8
#define SEG 1024

// Scratch (device globals; allocation-free per harness rules)
__device__ float  g_qkv[S_LEN * 3 * DMODEL];         // [S, 3*D] fp32 q|k|v
__device__ float  g_attn[S_LEN * DMODEL];            // attention out fp32
__device__ __half g_qk_h[S_LEN * 2 * DMODEL];        // [tok][ q(1024) | k(1024) ] half, roped (+q scaled)
__device__ __half g_vt[NSEG * NHEAD * DHEAD * SEG];  // [sg][h][d][tok_in_seg] half

// ---------------------------------------------------------------------------
// SGEMM (NT): C[m,n] = sum_k A[m,k]*B[n,k] + bias[n]   (fp32 exact, proven)
// ---------------------------------------------------------------------------
__global__ void __launch_bounds__(256) gemm_nt_bias(
    const float* __restrict__ A, const float* __restrict__ B,
    const float* __restrict__ bias, float* __restrict__ C,
    int M, int N, int K)
{
    __shared__ float As[8][128];
    __shared__ float Bs[8][128];

    const int t  = threadIdx.x;
    const int tx = t & 15;
    const int ty = t >> 4;
    const int m0 = blockIdx.y * 128;
    const int n0 = blockIdx.x * 128;

    const int lr = t >> 1;
    const int lk = (t & 1) * 4;

    const float* Ap = A + (size_t)(m0 + lr) * K + lk;
    const float* Bp = B + (size_t)(n0 + lr) * K + lk;

    float acc[8][8];
#pragma unroll
    for (int i = 0; i < 8; i++)
#pragma unroll
        for (int j = 0; j < 8; j++) acc[i][j] = 0.0f;

    for (int k0 = 0; k0 < K; k0 += 8) {
        float4 a = *(const float4*)(Ap + k0);
        float4 b = *(const float4*)(Bp + k0);
        As[lk + 0][lr] = a.x; As[lk + 1][lr] = a.y;
        As[lk + 2][lr] = a.z; As[lk + 3][lr] = a.w;
        Bs[lk + 0][lr] = b.x; Bs[lk + 1][lr] = b.y;
        Bs[lk + 2][lr] = b.z; Bs[lk + 3][lr] = b.w;
        __syncthreads();

#pragma unroll
        for (int kk = 0; kk < 8; kk++) {
            float ra[8], rb[8];
            *(float4*)(ra)     = *(const float4*)&As[kk][ty * 8];
            *(float4*)(ra + 4) = *(const float4*)&As[kk][ty * 8 + 4];
            *(float4*)(rb)     = *(const float4*)&Bs[kk][tx * 8];
            *(float4*)(rb + 4) = *(const float4*)&Bs[kk][tx * 8 + 4];
#pragma unroll
            for (int i = 0; i < 8; i++)
#pragma unroll
                for (int j = 0; j < 8; j++)
                    acc[i][j] = fmaf(ra[i], rb[j], acc[i][j]);
        }
        __syncthreads();
    }

#pragma unroll
    for (int i = 0; i < 8; i++) {
        int m = m0 + ty * 8 + i;
#pragma unroll
        for (int j = 0; j < 8; j += 4) {
            int n = n0 + tx * 8 + j;
            float4 o;
            o.x = acc[i][j + 0] + bias[n + 0];
            o.y = acc[i][j + 1] + bias[n + 1];
            o.z = acc[i][j + 2] + bias[n + 2];
            o.w = acc[i][j + 3] + bias[n + 3];
            *(float4*)&C[(size_t)m * N + n] = o;
        }
    }
}

// ---------------------------------------------------------------------------
// Prep 1: RoPE + scale(q) + fp16 convert for q,k.
// Thread per (tok, h, d<32): handles the (d, d+32) rotation pair for q and k.
// ---------------------------------------------------------------------------
__global__ void __launch_bounds__(256) prep_qk(
    const float* __restrict__ qkv, const float* __restrict__ cosT,
    const float* __restrict__ sinT, __half* __restrict__ qk)
{
    int idx = blockIdx.x * 256 + threadIdx.x;
    int d   = idx & 31;
    int h   = (idx >> 5) & 15;
    int tok = idx >> 9;

    const float* src = qkv + (size_t)tok * (3 * DMODEL) + h * DHEAD;
    float c1 = cosT[tok * DHEAD + d];
    float s1 = sinT[tok * DHEAD + d];
    float c2 = cosT[tok * DHEAD + d + 32];
    float s2 = sinT[tok * DHEAD + d + 32];

    float q1 = src[d], q2 = src[d + 32];
    __half* dq = qk + (size_t)tok * (2 * DMODEL) + h * DHEAD;
    dq[d]      = __float2half((q1 * c1 - q2 * s1) * 0.125f);
    dq[d + 32] = __float2half((q2 * c2 + q1 * s2) * 0.125f);

    float k1 = src[DMODEL + d], k2 = src[DMODEL + d + 32];
    __half* dk = dq + DMODEL;
    dk[d]      = __float2half(k1 * c1 - k2 * s1);
    dk[d + 32] = __float2half(k2 * c2 + k1 * s2);
}

// ---------------------------------------------------------------------------
// Prep 2: transpose V per (head) into [sg][h][d][tok], fp16.
// Block = (64-token chunk, head). smem 64x65 fp32 tile transpose.
// ---------------------------------------------------------------------------
__global__ void __launch_bounds__(256) prep_vt(
    const float* __restrict__ qkv, __half* __restrict__ vt)
{
    __shared__ float tile[64][65];
    const int tc = blockIdx.x;   // token chunk (64 tokens)
    const int h  = blockIdx.y;
    const int t  = threadIdx.x;

#pragma unroll
    for (int i = 0; i < 4; i++) {
        int f  = t + i * 256;
        int r  = f >> 4;
        int c4 = (f & 15) * 4;
        float4 v = *(const float4*)(qkv + (size_t)(tc * 64 + r) * (3 * DMODEL)
                                    + 2 * DMODEL + h * DHEAD + c4);
        tile[r][c4 + 0] = v.x; tile[r][c4 + 1] = v.y;
        tile[r][c4 + 2] = v.z; tile[r][c4 + 3] = v.w;
    }
    __syncthreads();

    const int sg  = (tc * 64) / SEG;
    const int tin = (tc * 64) % SEG;
#pragma unroll
    for (int i = 0; i < 4; i++) {
        int f  = t + i * 256;
        int d  = f >> 4;
        int t4 = (f & 15) * 4;
        __half2 a = __floats2half2_rn(tile[t4 + 0][d], tile[t4 + 1][d]);
        __half2 b = __floats2half2_rn(tile[t4 + 2][d], tile[t4 + 3][d]);
        __half2* dst = (__half2*)(vt + ((size_t)(sg * NHEAD + h) * DHEAD + d) * SEG
                                  + tin + t4);
        dst[0] = a;
        dst[1] = b;
    }
}

// ---------------------------------------------------------------------------
// fp16 m16n8k16 mma, fp32 accumulate
// ---------------------------------------------------------------------------
__device__ __forceinline__ void mma_f16(
    float c[4], unsigned a0, unsigned a1, unsigned a2, unsigned a3,
    unsigned b0, unsigned b1)
{
    asm volatile(
        "mma.sync.aligned.m16n8k16.row.col.f32.f16.f16.f32 "
        "{%0,%1,%2,%3},{%4,%5,%6,%7},{%8,%9},{%0,%1,%2,%3};"
        : "+f"(c[0]), "+f"(c[1]), "+f"(c[2]), "+f"(c[3])
        : "r"(a0), "r"(a1), "r"(a2), "r"(a3), "r"(b0), "r"(b1));
}

__device__ __forceinline__ unsigned pack_h2(float lo, float hi) {
    __half2 h = __floats2half2_rn(lo, hi);
    return *(unsigned*)&h;
}

// ---------------------------------------------------------------------------
// fp16 tensor-core flash attention.
// Block: 256 thr = 8 warps; Q tile 128 rows (warp owns m16); 64-key tiles,
// double-buffered K/V smem (stride 72 halves = conflict-free frag LDS).
// ---------------------------------------------------------------------------
#define HST 72                       // halves per smem row
#define KTILE_H (64 * HST)           // 4608 halves per K/V stage

__global__ void __launch_bounds__(256, 2) attn_f16_kernel(
    const __half* __restrict__ qk, const __half* __restrict__ vt,
    float* __restrict__ out)
{
    __shared__ __half sm[4 * KTILE_H];   // K[0],K[1],V[0],V[1]  (36864 B)
    __half* Qs = sm;                     // prologue overlay (128 x 72 = 9216)

    const int mt = blockIdx.x;   // q tile (0..7)
    const int h  = blockIdx.y;
    const int sg = blockIdx.z;

    const int t    = threadIdx.x;
    const int lane = t & 31;
    const int warp = t >> 5;
    const int g    = lane >> 2;
    const int tg   = lane & 3;

    const __half* kbase = qk + DMODEL + h * DHEAD;   // + tok*2048
    const __half* vbase = vt + (size_t)(sg * NHEAD + h) * DHEAD * SEG;

    // ---- Q tile: gmem -> smem (plain copy; already roped+scaled+fp16) ----
#pragma unroll
    for (int i = 0; i < 4; i++) {
        int f  = t + i * 256;        // 0..1023
        int r  = f >> 3;             // row 0..127
        int c8 = (f & 7) * 8;        // halves
        int tok = sg * SEG + mt * 128 + r;
        uint4 v = *(const uint4*)(qk + (size_t)tok * (2 * DMODEL) + h * DHEAD + c8);
        *(uint4*)&Qs[r * HST + c8] = v;
    }
    __syncthreads();

    // ---- prefetch tile 0 (regs) while extracting Q fragments ----
    uint4 rk[2], rv[2];
    {
        const int r  = t >> 3;        // uses tasks t, t+256 -> rows r, r+32
        const int c8 = (t & 7) * 8;
        rk[0] = *(const uint4*)(kbase + (size_t)(sg * SEG + r) * (2 * DMODEL) + c8);
        rk[1] = *(const uint4*)(kbase + (size_t)(sg * SEG + r + 32) * (2 * DMODEL) + c8);
        rv[0] = *(const uint4*)(vbase + (size_t)r * SEG + c8);
        rv[1] = *(const uint4*)(vbase + (size_t)(r + 32) * SEG + c8);
    }

    // Q A-fragments: 4 k-steps of m16k16
    unsigned qa[4][4];
    {
        int row = warp * 16 + g;
#pragma unroll
        for (int ks = 0; ks < 4; ks++) {
            int c = ks * 16 + 2 * tg;
            qa[ks][0] = *(const unsigned*)&Qs[row * HST + c];
            qa[ks][1] = *(const unsigned*)&Qs[(row + 8) * HST + c];
            qa[ks][2] = *(const unsigned*)&Qs[row * HST + c + 8];
            qa[ks][3] = *(const unsigned*)&Qs[(row + 8) * HST + c + 8];
        }
    }
    __syncthreads();

    // store tile 0 into stage 0
    {
        const int r  = t >> 3;
        const int c8 = (t & 7) * 8;
        *(uint4*)&sm[0 * KTILE_H + r * HST + c8]        = rk[0];
        *(uint4*)&sm[0 * KTILE_H + (r + 32) * HST + c8] = rk[1];
        *(uint4*)&sm[2 * KTILE_H + r * HST + c8]        = rv[0];
        *(uint4*)&sm[2 * KTILE_H + (r + 32) * HST + c8] = rv[1];
    }
    __syncthreads();

    float acc[8][4];
#pragma unroll
    for (int nb = 0; nb < 8; nb++)
#pragma unroll
        for (int i = 0; i < 4; i++) acc[nb][i] = 0.0f;
    float m_lo = -INFINITY, m_hi = -INFINITY, l_lo = 0.0f, l_hi = 0.0f;

    for (int jt = 0; jt < 16; jt++) {
        // prefetch next tile
        if (jt < 15) {
            const int r  = t >> 3;
            const int c8 = (t & 7) * 8;
            int j0n = (jt + 1) * 64;
            rk[0] = *(const uint4*)(kbase + (size_t)(sg * SEG + j0n + r) * (2 * DMODEL) + c8);
            rk[1] = *(const uint4*)(kbase + (size_t)(sg * SEG + j0n + r + 32) * (2 * DMODEL) + c8);
            rv[0] = *(const uint4*)(vbase + (size_t)r * SEG + j0n + c8);
            rv[1] = *(const uint4*)(vbase + (size_t)(r + 32) * SEG + j0n + c8);
        }

        const __half* Kst = sm + (jt & 1) * KTILE_H;
        const __half* Vst = sm + 2 * KTILE_H + (jt & 1) * KTILE_H;

        // ---- S = Q K^T ----
        float sf[8][4];
#pragma unroll
        for (int nb = 0; nb < 8; nb++) {
            sf[nb][0] = sf[nb][1] = sf[nb][2] = sf[nb][3] = 0.0f;
            const __half* kp = &Kst[(nb * 8 + g) * HST];
#pragma unroll
            for (int ks = 0; ks < 4; ks++) {
                unsigned b0 = *(const unsigned*)&kp[ks * 16 + 2 * tg];
                unsigned b1 = *(const unsigned*)&kp[ks * 16 + 2 * tg + 8];
                mma_f16(sf[nb], qa[ks][0], qa[ks][1], qa[ks][2], qa[ks][3], b0, b1);
            }
        }

        // ---- online softmax ----
        float tmax_lo = -INFINITY, tmax_hi = -INFINITY;
#pragma unroll
        for (int nb = 0; nb < 8; nb++) {
            tmax_lo = fmaxf(tmax_lo, fmaxf(sf[nb][0], sf[nb][1]));
            tmax_hi = fmaxf(tmax_hi, fmaxf(sf[nb][2], sf[nb][3]));
        }
        tmax_lo = fmaxf(tmax_lo, __shfl_xor_sync(0xffffffffu, tmax_lo, 1));
        tmax_lo = fmaxf(tmax_lo, __shfl_xor_sync(0xffffffffu, tmax_lo, 2));
        tmax_hi = fmaxf(tmax_hi, __shfl_xor_sync(0xffffffffu, tmax_hi, 1));
        tmax_hi = fmaxf(tmax_hi, __shfl_xor_sync(0xffffffffu, tmax_hi, 2));

        float mn_lo = fmaxf(m_lo, tmax_lo);
        float mn_hi = fmaxf(m_hi, tmax_hi);
        float fac_lo = __expf(m_lo - mn_lo);
        float fac_hi = __expf(m_hi - mn_hi);
        m_lo = mn_lo; m_hi = mn_hi;

        float rs_lo = 0.0f, rs_hi = 0.0f;
#pragma unroll
        for (int nb = 0; nb < 8; nb++) {
            sf[nb][0] = __expf(sf[nb][0] - m_lo);
            sf[nb][1] = __expf(sf[nb][1] - m_lo);
            sf[nb][2] = __expf(sf[nb][2] - m_hi);
            sf[nb][3] = __expf(sf[nb][3] - m_hi);
            rs_lo += sf[nb][0] + sf[nb][1];
            rs_hi += sf[nb][2] + sf[nb][3];
        }
        rs_lo += __shfl_xor_sync(0xffffffffu, rs_lo, 1);
        rs_lo += __shfl_xor_sync(0xffffffffu, rs_lo, 2);
        rs_hi += __shfl_xor_sync(0xffffffffu, rs_hi, 1);
        rs_hi += __shfl_xor_sync(0xffffffffu, rs_hi, 2);

        l_lo = l_lo * fac_lo + rs_lo;
        l_hi = l_hi * fac_hi + rs_hi;
#pragma unroll
        for (int nb = 0; nb < 8; nb++) {
            acc[nb][0] *= fac_lo; acc[nb][1] *= fac_lo;
            acc[nb][2] *= fac_hi; acc[nb][3] *= fac_hi;
        }

        // ---- acc += P V ; P C-frags map directly to fp16 A-frags ----
#pragma unroll
        for (int kc = 0; kc < 4; kc++) {
            unsigned pa0 = pack_h2(sf[2 * kc][0],     sf[2 * kc][1]);
            unsigned pa1 = pack_h2(sf[2 * kc][2],     sf[2 * kc][3]);
            unsigned pa2 = pack_h2(sf[2 * kc + 1][0], sf[2 * kc + 1][1]);
            unsigned pa3 = pack_h2(sf[2 * kc + 1][2], sf[2 * kc + 1][3]);
#pragma unroll
            for (int nb = 0; nb < 8; nb++) {
                const __half* vp = &Vst[(nb * 8 + g) * HST + kc * 16];
                unsigned vb0 = *(const unsigned*)&vp[2 * tg];
                unsigned vb1 = *(const unsigned*)&vp[2 * tg + 8];
                mma_f16(acc[nb], pa0, pa1, pa2, pa3, vb0, vb1);
            }
        }

        // store prefetched tile into other stage
        if (jt < 15) {
            __half* Kd = sm + ((jt + 1) & 1) * KTILE_H;
            __half* Vd = sm + 2 * KTILE_H + ((jt + 1) & 1) * KTILE_H;
            const int r  = t >> 3;
            const int c8 = (t & 7) * 8;
            *(uint4*)&Kd[r * HST + c8]        = rk[0];
            *(uint4*)&Kd[(r + 32) * HST + c8] = rk[1];
            *(uint4*)&Vd[r * HST + c8]        = rv[0];
            *(uint4*)&Vd[(r + 32) * HST + c8] = rv[1];
        }
        __syncthreads();
    }

    // ---- Epilogue ----
    float inv_lo = 1.0f / l_lo;
    float inv_hi = 1.0f / l_hi;
    int tok_lo = sg * SEG + mt * 128 + warp * 16 + g;
#pragma unroll
    for (int nb = 0; nb < 8; nb++) {
        int col = h * DHEAD + nb * 8 + tg * 2;
        float2 o;
        o.x = acc[nb][0] * inv_lo;
        o.y = acc[nb][1] * inv_lo;
        *(float2*)&out[(size_t)tok_lo * DMODEL + col] = o;
        o.x = acc[nb][2] * inv_hi;
        o.y = acc[nb][3] * inv_hi;
        *(float2*)&out[(size_t)(tok_lo + 8) * DMODEL + col] = o;
    }
}

// ---------------------------------------------------------------------------
// Launch
// ---------------------------------------------------------------------------
extern "C" void kernel_launch(void* const* d_in, const int* in_sizes, int n_in,
                              void* d_out, int out_size)
{
    const float* hs     = (const float*)d_in[0];
    const float* cosT   = (const float*)d_in[1];
    const float* sinT   = (const float*)d_in[2];
    const float* qkv_w  = (const float*)d_in[3];
    const float* qkv_b  = (const float*)d_in[4];
    const float* proj_w = (const float*)d_in[5];
    const float* proj_b = (const float*)d_in[6];
    float* out = (float*)d_out;

    void *qkvp_v, *attnp_v, *qkh_v, *vt_v;
    cudaGetSymbolAddress(&qkvp_v, g_qkv);
    cudaGetSymbolAddress(&attnp_v, g_attn);
    cudaGetSymbolAddress(&qkh_v, g_qk_h);
    cudaGetSymbolAddress(&vt_v, g_vt);
    float*  qkvp  = (float*)qkvp_v;
    float*  attnp = (float*)attnp_v;
    __half* qkh   = (__half*)qkh_v;
    __half* vtp   = (__half*)vt_v;

    // 1) QKV GEMM (fp32 exact)
    {
        dim3 grid(3 * DMODEL / 128, S_LEN / 128);
        gemm_nt_bias<<<grid, 256>>>(hs, qkv_w, qkv_b, qkvp,
                                    S_LEN, 3 * DMODEL, DMODEL);
    }

    // 2) Prep: RoPE+fp16 q/k, fp16 transposed v
    {
        prep_qk<<<(S_LEN * NHEAD * 32) / 256, 256>>>(qkvp, cosT, sinT, qkh);
        dim3 gv(S_LEN / 64, NHEAD);
        prep_vt<<<gv, 256>>>(qkvp, vtp);
    }

    // 3) Attention (fp16 tensor cores) -> g_attn
    {
        dim3 grid(SEG / 128, NHEAD, NSEG);
        attn_f16_kernel<<<grid, 256>>>(qkh, vtp, attnp);
    }

    // 4) Output projection (fp32 exact)
    {
        dim3 grid(DMODEL / 128, S_LEN / 128);
        gemm_nt_bias<<<grid, 256>>>(attnp, proj_w, proj_b, out,
                                    S_LEN, DMODEL, DMODEL);
    }
}

// round 5
// speedup vs baseline: 2.5566x; 1.7819x over previous
#include <cuda_runtime.h>
#include <cuda_fp16.h>
#include <cstdint>
#include <math.h>

// Problem constants
#define S_LEN 8192
#define DMODEL 1024
#define NHEAD 16
#define DHEAD 64
#define NSEG 8
#define SEG 1024

#define SPLIT_SC 1024.0f
#define SPLIT_INV (1.0f / 1024.0f)

// Scratch (device globals)
__device__ float  g_qkv[S_LEN * 3 * DMODEL];         // QKV GEMM out fp32
__device__ __half g_qk_h[S_LEN * 2 * DMODEL];        // roped q|k half
__device__ __half g_vt[NSEG * NHEAD * DHEAD * SEG];  // v transposed half
__device__ __half g_ah[S_LEN * DMODEL];              // A hi (hs, then attn-out)
__device__ __half g_al[S_LEN * DMODEL];              // A lo
__device__ __half g_wh[3 * DMODEL * DMODEL];         // qkv_w hi
__device__ __half g_wl[3 * DMODEL * DMODEL];         // qkv_w lo
__device__ __half g_ph[DMODEL * DMODEL];             // proj_w hi
__device__ __half g_pl[DMODEL * DMODEL];             // proj_w lo

// ---------------------------------------------------------------------------
// fp16 m16n8k16 mma, fp32 accumulate
// ---------------------------------------------------------------------------
__device__ __forceinline__ void mma_f16(
    float c[4], unsigned a0, unsigned a1, unsigned a2, unsigned a3,
    unsigned b0, unsigned b1)
{
    asm volatile(
        "mma.sync.aligned.m16n8k16.row.col.f32.f16.f16.f32 "
        "{%0,%1,%2,%3},{%4,%5,%6,%7},{%8,%9},{%0,%1,%2,%3};"
        : "+f"(c[0]), "+f"(c[1]), "+f"(c[2]), "+f"(c[3])
        : "r"(a0), "r"(a1), "r"(a2), "r"(a3), "r"(b0), "r"(b1));
}

__device__ __forceinline__ unsigned pack_h2(float lo, float hi) {
    __half2 h = __floats2half2_rn(lo, hi);
    return *(unsigned*)&h;
}

// ---------------------------------------------------------------------------
// Split fp32 -> (hi fp16, lo fp16 * 1024). 4 elements / thread.
// ---------------------------------------------------------------------------
__global__ void __launch_bounds__(256) split_fp16(
    const float* __restrict__ x, __half* __restrict__ hi,
    __half* __restrict__ lo, int n4)
{
    int i = blockIdx.x * 256 + threadIdx.x;
    if (i >= n4) return;
    float4 v = ((const float4*)x)[i];
    __half h0 = __float2half_rn(v.x);
    __half h1 = __float2half_rn(v.y);
    __half h2 = __float2half_rn(v.z);
    __half h3 = __float2half_rn(v.w);
    __half2* hp = (__half2*)(hi + 4 * (size_t)i);
    hp[0] = __halves2half2(h0, h1);
    hp[1] = __halves2half2(h2, h3);
    __half2* lp = (__half2*)(lo + 4 * (size_t)i);
    lp[0] = __floats2half2_rn((v.x - __half2float(h0)) * SPLIT_SC,
                              (v.y - __half2float(h1)) * SPLIT_SC);
    lp[1] = __floats2half2_rn((v.z - __half2float(h2)) * SPLIT_SC,
                              (v.w - __half2float(h3)) * SPLIT_SC);
}

// ---------------------------------------------------------------------------
// Split-fp16 tensor-core GEMM (NT): C = A * B^T + bias, near-fp32 accuracy.
// A = Ah + Al*2^-10, B = Bh + Bl*2^-10 ; C = Ah*Bh + 2^-10 (Ah*Bl + Al*Bh).
// BM=128, BN=64, BK=32; 256 thr = 8 warps (4m x 2n), warp tile 32x32.
// Ping-pong smem (2 stages x {Ah,Al:128x40 | Bh,Bl:64x40} halves = 61440 B).
// ---------------------------------------------------------------------------
#define GST 40                        // halves per smem row
#define STG_H 15360                   // halves per stage
#define GEMM_SMEM_BYTES (2 * STG_H * 2)

__global__ void __launch_bounds__(256) gemm_split_nt(
    const __half* __restrict__ Ah, const __half* __restrict__ Al,
    const __half* __restrict__ Bh, const __half* __restrict__ Bl,
    const float* __restrict__ bias, float* __restrict__ C,
    int M, int N, int K)
{
    extern __shared__ __half sg[];
    // stage layout (halves): Ah 0..5119 | Al 5120..10239 | Bh 10240..12799 | Bl 12800..15359

    const int t      = threadIdx.x;
    const int lane   = t & 31;
    const int warp   = t >> 5;
    const int warp_m = warp >> 1;     // 0..3
    const int warp_n = warp & 1;      // 0..1
    const int g      = lane >> 2;
    const int tg     = lane & 3;

    const int m0 = blockIdx.y * 128;
    const int n0 = blockIdx.x * 64;

    // load task mapping
    const int arow = t >> 1;              // A: ids t, t+256 -> rows t>>2.. (see below)
    (void)arow;

    uint4 ra_h[2], ra_l[2], rb_h, rb_l;

    // ---- helper lambdas (macros) ----
#define LOAD_REGS(k0)                                                          \
    {                                                                          \
        int id0 = t, id1 = t + 256;                                            \
        int r0 = id0 >> 2, c0 = (id0 & 3) * 8;                                 \
        int r1 = id1 >> 2, c1 = (id1 & 3) * 8;                                 \
        ra_h[0] = *(const uint4*)(Ah + (size_t)(m0 + r0) * K + (k0) + c0);     \
        ra_h[1] = *(const uint4*)(Ah + (size_t)(m0 + r1) * K + (k0) + c1);     \
        ra_l[0] = *(const uint4*)(Al + (size_t)(m0 + r0) * K + (k0) + c0);     \
        ra_l[1] = *(const uint4*)(Al + (size_t)(m0 + r1) * K + (k0) + c1);     \
        int rb = t >> 2, cb = (t & 3) * 8;                                     \
        rb_h = *(const uint4*)(Bh + (size_t)(n0 + rb) * K + (k0) + cb);        \
        rb_l = *(const uint4*)(Bl + (size_t)(n0 + rb) * K + (k0) + cb);        \
    }

#define STORE_REGS(st)                                                         \
    {                                                                          \
        __half* base = sg + (st) * STG_H;                                      \
        int id0 = t, id1 = t + 256;                                            \
        int r0 = id0 >> 2, c0 = (id0 & 3) * 8;                                 \
        int r1 = id1 >> 2, c1 = (id1 & 3) * 8;                                 \
        *(uint4*)&base[r0 * GST + c0]        = ra_h[0];                        \
        *(uint4*)&base[r1 * GST + c1]        = ra_h[1];                        \
        *(uint4*)&base[5120 + r0 * GST + c0] = ra_l[0];                        \
        *(uint4*)&base[5120 + r1 * GST + c1] = ra_l[1];                        \
        int rb = t >> 2, cb = (t & 3) * 8;                                     \
        *(uint4*)&base[10240 + rb * GST + cb] = rb_h;                          \
        *(uint4*)&base[12800 + rb * GST + cb] = rb_l;                          \
    }

    float accm[2][4][4], accc[2][4][4];
#pragma unroll
    for (int mi = 0; mi < 2; mi++)
#pragma unroll
        for (int nb = 0; nb < 4; nb++)
#pragma unroll
            for (int i = 0; i < 4; i++) { accm[mi][nb][i] = 0.0f; accc[mi][nb][i] = 0.0f; }

    LOAD_REGS(0);
    STORE_REGS(0);
    __syncthreads();

    const int n_iter = K / 32;
    for (int it = 0; it < n_iter; it++) {
        if (it < n_iter - 1) LOAD_REGS((it + 1) * 32);

        const __half* base = sg + (it & 1) * STG_H;
        const __half* As_h = base;
        const __half* As_l = base + 5120;
        const __half* Bs_h = base + 10240;
        const __half* Bs_l = base + 12800;

#pragma unroll
        for (int ks = 0; ks < 2; ks++) {
            const int kc = ks * 16 + 2 * tg;
            unsigned ah[2][4], al[2][4];
#pragma unroll
            for (int mi = 0; mi < 2; mi++) {
                int r = warp_m * 32 + mi * 16 + g;
                ah[mi][0] = *(const unsigned*)&As_h[r * GST + kc];
                ah[mi][1] = *(const unsigned*)&As_h[(r + 8) * GST + kc];
                ah[mi][2] = *(const unsigned*)&As_h[r * GST + kc + 8];
                ah[mi][3] = *(const unsigned*)&As_h[(r + 8) * GST + kc + 8];
                al[mi][0] = *(const unsigned*)&As_l[r * GST + kc];
                al[mi][1] = *(const unsigned*)&As_l[(r + 8) * GST + kc];
                al[mi][2] = *(const unsigned*)&As_l[r * GST + kc + 8];
                al[mi][3] = *(const unsigned*)&As_l[(r + 8) * GST + kc + 8];
            }
#pragma unroll
            for (int nb = 0; nb < 4; nb++) {
                int r = warp_n * 32 + nb * 8 + g;
                unsigned bh0 = *(const unsigned*)&Bs_h[r * GST + kc];
                unsigned bh1 = *(const unsigned*)&Bs_h[r * GST + kc + 8];
                unsigned bl0 = *(const unsigned*)&Bs_l[r * GST + kc];
                unsigned bl1 = *(const unsigned*)&Bs_l[r * GST + kc + 8];
#pragma unroll
                for (int mi = 0; mi < 2; mi++) {
                    mma_f16(accm[mi][nb], ah[mi][0], ah[mi][1], ah[mi][2], ah[mi][3], bh0, bh1);
                    mma_f16(accc[mi][nb], ah[mi][0], ah[mi][1], ah[mi][2], ah[mi][3], bl0, bl1);
                    mma_f16(accc[mi][nb], al[mi][0], al[mi][1], al[mi][2], al[mi][3], bh0, bh1);
                }
            }
        }

        if (it < n_iter - 1) STORE_REGS((it + 1) & 1);
        __syncthreads();
    }

    // ---- Epilogue: C = accm + accc * 2^-10 + bias ----
#pragma unroll
    for (int mi = 0; mi < 2; mi++) {
        int row = m0 + warp_m * 32 + mi * 16 + g;
#pragma unroll
        for (int nb = 0; nb < 4; nb++) {
            int n = n0 + warp_n * 32 + nb * 8 + 2 * tg;
            float b0 = bias[n], b1 = bias[n + 1];
            float2 v;
            v.x = accm[mi][nb][0] + accc[mi][nb][0] * SPLIT_INV + b0;
            v.y = accm[mi][nb][1] + accc[mi][nb][1] * SPLIT_INV + b1;
            *(float2*)&C[(size_t)row * N + n] = v;
            v.x = accm[mi][nb][2] + accc[mi][nb][2] * SPLIT_INV + b0;
            v.y = accm[mi][nb][3] + accc[mi][nb][3] * SPLIT_INV + b1;
            *(float2*)&C[(size_t)(row + 8) * N + n] = v;
        }
    }
#undef LOAD_REGS
#undef STORE_REGS
}

// ---------------------------------------------------------------------------
// Prep 1: RoPE + scale(q) + fp16 convert for q,k.
// ---------------------------------------------------------------------------
__global__ void __launch_bounds__(256) prep_qk(
    const float* __restrict__ qkv, const float* __restrict__ cosT,
    const float* __restrict__ sinT, __half* __restrict__ qk)
{
    int idx = blockIdx.x * 256 + threadIdx.x;
    int d   = idx & 31;
    int h   = (idx >> 5) & 15;
    int tok = idx >> 9;

    const float* src = qkv + (size_t)tok * (3 * DMODEL) + h * DHEAD;
    float c1 = cosT[tok * DHEAD + d];
    float s1 = sinT[tok * DHEAD + d];
    float c2 = cosT[tok * DHEAD + d + 32];
    float s2 = sinT[tok * DHEAD + d + 32];

    float q1 = src[d], q2 = src[d + 32];
    __half* dq = qk + (size_t)tok * (2 * DMODEL) + h * DHEAD;
    dq[d]      = __float2half((q1 * c1 - q2 * s1) * 0.125f);
    dq[d + 32] = __float2half((q2 * c2 + q1 * s2) * 0.125f);

    float k1 = src[DMODEL + d], k2 = src[DMODEL + d + 32];
    __half* dk = dq + DMODEL;
    dk[d]      = __float2half(k1 * c1 - k2 * s1);
    dk[d + 32] = __float2half(k2 * c2 + k1 * s2);
}

// ---------------------------------------------------------------------------
// Prep 2: transpose V per head into [sg][h][d][tok], fp16.
// ---------------------------------------------------------------------------
__global__ void __launch_bounds__(256) prep_vt(
    const float* __restrict__ qkv, __half* __restrict__ vt)
{
    __shared__ float tile[64][65];
    const int tc = blockIdx.x;
    const int h  = blockIdx.y;
    const int t  = threadIdx.x;

#pragma unroll
    for (int i = 0; i < 4; i++) {
        int f  = t + i * 256;
        int r  = f >> 4;
        int c4 = (f & 15) * 4;
        float4 v = *(const float4*)(qkv + (size_t)(tc * 64 + r) * (3 * DMODEL)
                                    + 2 * DMODEL + h * DHEAD + c4);
        tile[r][c4 + 0] = v.x; tile[r][c4 + 1] = v.y;
        tile[r][c4 + 2] = v.z; tile[r][c4 + 3] = v.w;
    }
    __syncthreads();

    const int sg  = (tc * 64) / SEG;
    const int tin = (tc * 64) % SEG;
#pragma unroll
    for (int i = 0; i < 4; i++) {
        int f  = t + i * 256;
        int d  = f >> 4;
        int t4 = (f & 15) * 4;
        __half2 a = __floats2half2_rn(tile[t4 + 0][d], tile[t4 + 1][d]);
        __half2 b = __floats2half2_rn(tile[t4 + 2][d], tile[t4 + 3][d]);
        __half2* dst = (__half2*)(vt + ((size_t)(sg * NHEAD + h) * DHEAD + d) * SEG
                                  + tin + t4);
        dst[0] = a;
        dst[1] = b;
    }
}

// ---------------------------------------------------------------------------
// fp16 tensor-core flash attention; epilogue emits split-fp16 proj input.
// ---------------------------------------------------------------------------
#define HST 72
#define KTILE_H (64 * HST)

__global__ void __launch_bounds__(256, 2) attn_f16_kernel(
    const __half* __restrict__ qk, const __half* __restrict__ vt,
    __half* __restrict__ oh, __half* __restrict__ ol)
{
    __shared__ __half sm[4 * KTILE_H];
    __half* Qs = sm;

    const int mt = blockIdx.x;
    const int h  = blockIdx.y;
    const int sg = blockIdx.z;

    const int t    = threadIdx.x;
    const int lane = t & 31;
    const int warp = t >> 5;
    const int g    = lane >> 2;
    const int tg   = lane & 3;

    const __half* kbase = qk + DMODEL + h * DHEAD;
    const __half* vbase = vt + (size_t)(sg * NHEAD + h) * DHEAD * SEG;

#pragma unroll
    for (int i = 0; i < 4; i++) {
        int f  = t + i * 256;
        int r  = f >> 3;
        int c8 = (f & 7) * 8;
        int tok = sg * SEG + mt * 128 + r;
        uint4 v = *(const uint4*)(qk + (size_t)tok * (2 * DMODEL) + h * DHEAD + c8);
        *(uint4*)&Qs[r * HST + c8] = v;
    }
    __syncthreads();

    uint4 rk[2], rv[2];
    {
        const int r  = t >> 3;
        const int c8 = (t & 7) * 8;
        rk[0] = *(const uint4*)(kbase + (size_t)(sg * SEG + r) * (2 * DMODEL) + c8);
        rk[1] = *(const uint4*)(kbase + (size_t)(sg * SEG + r + 32) * (2 * DMODEL) + c8);
        rv[0] = *(const uint4*)(vbase + (size_t)r * SEG + c8);
        rv[1] = *(const uint4*)(vbase + (size_t)(r + 32) * SEG + c8);
    }

    unsigned qa[4][4];
    {
        int row = warp * 16 + g;
#pragma unroll
        for (int ks = 0; ks < 4; ks++) {
            int c = ks * 16 + 2 * tg;
            qa[ks][0] = *(const unsigned*)&Qs[row * HST + c];
            qa[ks][1] = *(const unsigned*)&Qs[(row + 8) * HST + c];
            qa[ks][2] = *(const unsigned*)&Qs[row * HST + c + 8];
            qa[ks][3] = *(const unsigned*)&Qs[(row + 8) * HST + c + 8];
        }
    }
    __syncthreads();

    {
        const int r  = t >> 3;
        const int c8 = (t & 7) * 8;
        *(uint4*)&sm[0 * KTILE_H + r * HST + c8]        = rk[0];
        *(uint4*)&sm[0 * KTILE_H + (r + 32) * HST + c8] = rk[1];
        *(uint4*)&sm[2 * KTILE_H + r * HST + c8]        = rv[0];
        *(uint4*)&sm[2 * KTILE_H + (r + 32) * HST + c8] = rv[1];
    }
    __syncthreads();

    float acc[8][4];
#pragma unroll
    for (int nb = 0; nb < 8; nb++)
#pragma unroll
        for (int i = 0; i < 4; i++) acc[nb][i] = 0.0f;
    float m_lo = -INFINITY, m_hi = -INFINITY, l_lo = 0.0f, l_hi = 0.0f;

    for (int jt = 0; jt < 16; jt++) {
        if (jt < 15) {
            const int r  = t >> 3;
            const int c8 = (t & 7) * 8;
            int j0n = (jt + 1) * 64;
            rk[0] = *(const uint4*)(kbase + (size_t)(sg * SEG + j0n + r) * (2 * DMODEL) + c8);
            rk[1] = *(const uint4*)(kbase + (size_t)(sg * SEG + j0n + r + 32) * (2 * DMODEL) + c8);
            rv[0] = *(const uint4*)(vbase + (size_t)r * SEG + j0n + c8);
            rv[1] = *(const uint4*)(vbase + (size_t)(r + 32) * SEG + j0n + c8);
        }

        const __half* Kst = sm + (jt & 1) * KTILE_H;
        const __half* Vst = sm + 2 * KTILE_H + (jt & 1) * KTILE_H;

        float sf[8][4];
#pragma unroll
        for (int nb = 0; nb < 8; nb++) {
            sf[nb][0] = sf[nb][1] = sf[nb][2] = sf[nb][3] = 0.0f;
            const __half* kp = &Kst[(nb * 8 + g) * HST];
#pragma unroll
            for (int ks = 0; ks < 4; ks++) {
                unsigned b0 = *(const unsigned*)&kp[ks * 16 + 2 * tg];
                unsigned b1 = *(const unsigned*)&kp[ks * 16 + 2 * tg + 8];
                mma_f16(sf[nb], qa[ks][0], qa[ks][1], qa[ks][2], qa[ks][3], b0, b1);
            }
        }

        float tmax_lo = -INFINITY, tmax_hi = -INFINITY;
#pragma unroll
        for (int nb = 0; nb < 8; nb++) {
            tmax_lo = fmaxf(tmax_lo, fmaxf(sf[nb][0], sf[nb][1]));
            tmax_hi = fmaxf(tmax_hi, fmaxf(sf[nb][2], sf[nb][3]));
        }
        tmax_lo = fmaxf(tmax_lo, __shfl_xor_sync(0xffffffffu, tmax_lo, 1));
        tmax_lo = fmaxf(tmax_lo, __shfl_xor_sync(0xffffffffu, tmax_lo, 2));
        tmax_hi = fmaxf(tmax_hi, __shfl_xor_sync(0xffffffffu, tmax_hi, 1));
        tmax_hi = fmaxf(tmax_hi, __shfl_xor_sync(0xffffffffu, tmax_hi, 2));

        float mn_lo = fmaxf(m_lo, tmax_lo);
        float mn_hi = fmaxf(m_hi, tmax_hi);
        float fac_lo = __expf(m_lo - mn_lo);
        float fac_hi = __expf(m_hi - mn_hi);
        m_lo = mn_lo; m_hi = mn_hi;

        float rs_lo = 0.0f, rs_hi = 0.0f;
#pragma unroll
        for (int nb = 0; nb < 8; nb++) {
            sf[nb][0] = __expf(sf[nb][0] - m_lo);
            sf[nb][1] = __expf(sf[nb][1] - m_lo);
            sf[nb][2] = __expf(sf[nb][2] - m_hi);
            sf[nb][3] = __expf(sf[nb][3] - m_hi);
            rs_lo += sf[nb][0] + sf[nb][1];
            rs_hi += sf[nb][2] + sf[nb][3];
        }
        rs_lo += __shfl_xor_sync(0xffffffffu, rs_lo, 1);
        rs_lo += __shfl_xor_sync(0xffffffffu, rs_lo, 2);
        rs_hi += __shfl_xor_sync(0xffffffffu, rs_hi, 1);
        rs_hi += __shfl_xor_sync(0xffffffffu, rs_hi, 2);

        l_lo = l_lo * fac_lo + rs_lo;
        l_hi = l_hi * fac_hi + rs_hi;
#pragma unroll
        for (int nb = 0; nb < 8; nb++) {
            acc[nb][0] *= fac_lo; acc[nb][1] *= fac_lo;
            acc[nb][2] *= fac_hi; acc[nb][3] *= fac_hi;
        }

#pragma unroll
        for (int kc = 0; kc < 4; kc++) {
            unsigned pa0 = pack_h2(sf[2 * kc][0],     sf[2 * kc][1]);
            unsigned pa1 = pack_h2(sf[2 * kc][2],     sf[2 * kc][3]);
            unsigned pa2 = pack_h2(sf[2 * kc + 1][0], sf[2 * kc + 1][1]);
            unsigned pa3 = pack_h2(sf[2 * kc + 1][2], sf[2 * kc + 1][3]);
#pragma unroll
            for (int nb = 0; nb < 8; nb++) {
                const __half* vp = &Vst[(nb * 8 + g) * HST + kc * 16];
                unsigned vb0 = *(const unsigned*)&vp[2 * tg];
                unsigned vb1 = *(const unsigned*)&vp[2 * tg + 8];
                mma_f16(acc[nb], pa0, pa1, pa2, pa3, vb0, vb1);
            }
        }

        if (jt < 15) {
            __half* Kd = sm + ((jt + 1) & 1) * KTILE_H;
            __half* Vd = sm + 2 * KTILE_H + ((jt + 1) & 1) * KTILE_H;
            const int r  = t >> 3;
            const int c8 = (t & 7) * 8;
            *(uint4*)&Kd[r * HST + c8]        = rk[0];
            *(uint4*)&Kd[(r + 32) * HST + c8] = rk[1];
            *(uint4*)&Vd[r * HST + c8]        = rv[0];
            *(uint4*)&Vd[(r + 32) * HST + c8] = rv[1];
        }
        __syncthreads();
    }

    // ---- Epilogue: split-fp16 output for proj GEMM ----
    float inv_lo = 1.0f / l_lo;
    float inv_hi = 1.0f / l_hi;
    int tok_lo = sg * SEG + mt * 128 + warp * 16 + g;
#pragma unroll
    for (int nb = 0; nb < 8; nb++) {
        int col = h * DHEAD + nb * 8 + tg * 2;
        {
            float v0 = acc[nb][0] * inv_lo, v1 = acc[nb][1] * inv_lo;
            __half h0 = __float2half_rn(v0), h1 = __float2half_rn(v1);
            *(__half2*)&oh[(size_t)tok_lo * DMODEL + col] = __halves2half2(h0, h1);
            *(__half2*)&ol[(size_t)tok_lo * DMODEL + col] =
                __floats2half2_rn((v0 - __half2float(h0)) * SPLIT_SC,
                                  (v1 - __half2float(h1)) * SPLIT_SC);
        }
        {
            float v0 = acc[nb][2] * inv_hi, v1 = acc[nb][3] * inv_hi;
            __half h0 = __float2half_rn(v0), h1 = __float2half_rn(v1);
            *(__half2*)&oh[(size_t)(tok_lo + 8) * DMODEL + col] = __halves2half2(h0, h1);
            *(__half2*)&ol[(size_t)(tok_lo + 8) * DMODEL + col] =
                __floats2half2_rn((v0 - __half2float(h0)) * SPLIT_SC,
                                  (v1 - __half2float(h1)) * SPLIT_SC);
        }
    }
}

// ---------------------------------------------------------------------------
// Launch
// ---------------------------------------------------------------------------
extern "C" void kernel_launch(void* const* d_in, const int* in_sizes, int n_in,
                              void* d_out, int out_size)
{
    const float* hs     = (const float*)d_in[0];
    const float* cosT   = (const float*)d_in[1];
    const float* sinT   = (const float*)d_in[2];
    const float* qkv_w  = (const float*)d_in[3];
    const float* qkv_b  = (const float*)d_in[4];
    const float* proj_w = (const float*)d_in[5];
    const float* proj_b = (const float*)d_in[6];
    float* out = (float*)d_out;

    void *qkvp_v, *qkh_v, *vt_v, *ah_v, *al_v, *wh_v, *wl_v, *ph_v, *pl_v;
    cudaGetSymbolAddress(&qkvp_v, g_qkv);
    cudaGetSymbolAddress(&qkh_v, g_qk_h);
    cudaGetSymbolAddress(&vt_v, g_vt);
    cudaGetSymbolAddress(&ah_v, g_ah);
    cudaGetSymbolAddress(&al_v, g_al);
    cudaGetSymbolAddress(&wh_v, g_wh);
    cudaGetSymbolAddress(&wl_v, g_wl);
    cudaGetSymbolAddress(&ph_v, g_ph);
    cudaGetSymbolAddress(&pl_v, g_pl);
    float*  qkvp = (float*)qkvp_v;
    __half* qkh  = (__half*)qkh_v;
    __half* vtp  = (__half*)vt_v;
    __half* ahp  = (__half*)ah_v;
    __half* alp  = (__half*)al_v;
    __half* whp  = (__half*)wh_v;
    __half* wlp  = (__half*)wl_v;
    __half* php  = (__half*)ph_v;
    __half* plp  = (__half*)pl_v;

    cudaFuncSetAttribute(gemm_split_nt,
                         cudaFuncAttributeMaxDynamicSharedMemorySize,
                         GEMM_SMEM_BYTES);

    // 0) Splits
    split_fp16<<<(S_LEN * DMODEL / 4) / 256, 256>>>(hs, ahp, alp, S_LEN * DMODEL / 4);
    split_fp16<<<(3 * DMODEL * DMODEL / 4) / 256, 256>>>(qkv_w, whp, wlp, 3 * DMODEL * DMODEL / 4);
    split_fp16<<<(DMODEL * DMODEL / 4) / 256, 256>>>(proj_w, php, plp, DMODEL * DMODEL / 4);

    // 1) QKV GEMM (split fp16 tensor cores) -> g_qkv fp32
    {
        dim3 grid(3 * DMODEL / 64, S_LEN / 128);
        gemm_split_nt<<<grid, 256, GEMM_SMEM_BYTES>>>(
            ahp, alp, whp, wlp, qkv_b, qkvp, S_LEN, 3 * DMODEL, DMODEL);
    }

    // 2) Prep: RoPE+fp16 q/k, fp16 transposed v
    prep_qk<<<(S_LEN * NHEAD * 32) / 256, 256>>>(qkvp, cosT, sinT, qkh);
    {
        dim3 gv(S_LEN / 64, NHEAD);
        prep_vt<<<gv, 256>>>(qkvp, vtp);
    }

    // 3) Attention -> split-fp16 proj input (g_ah/g_al reused)
    {
        dim3 grid(SEG / 128, NHEAD, NSEG);
        attn_f16_kernel<<<grid, 256>>>(qkh, vtp, ahp, alp);
    }

    // 4) Output projection (split fp16 tensor cores) -> d_out fp32
    {
        dim3 grid(DMODEL / 64, S_LEN / 128);
        gemm_split_nt<<<grid, 256, GEMM_SMEM_BYTES>>>(
            ahp, alp, php, plp, proj_b, out, S_LEN, DMODEL, DMODEL);
    }
}

// round 7
// speedup vs baseline: 3.4629x; 1.3545x over previous
#include <cuda_runtime.h>
#include <cuda_fp16.h>
#include <cstdint>
#include <math.h>

// Problem constants
#define S_LEN 8192
#define DMODEL 1024
#define NHEAD 16
#define DHEAD 64
#define NSEG 8
#define SEG 1024

#define SPLIT_SC 1024.0f
#define SPLIT_INV (1.0f / 1024.0f)

// Scratch (device globals)
__device__ float  g_qkv[S_LEN * 3 * DMODEL];
__device__ __half g_qk_h[S_LEN * 2 * DMODEL];
__device__ __half g_vt[NSEG * NHEAD * DHEAD * SEG];
__device__ __half g_ah[S_LEN * DMODEL];
__device__ __half g_al[S_LEN * DMODEL];
__device__ __half g_wh[3 * DMODEL * DMODEL];
__device__ __half g_wl[3 * DMODEL * DMODEL];
__device__ __half g_ph[DMODEL * DMODEL];
__device__ __half g_pl[DMODEL * DMODEL];

// ---------------------------------------------------------------------------
// helpers
// ---------------------------------------------------------------------------
__device__ __forceinline__ uint32_t smem_u32(const void* p) {
    uint32_t a;
    asm("{ .reg .u64 tmp; cvta.to.shared.u64 tmp, %1; cvt.u32.u64 %0, tmp; }"
        : "=r"(a) : "l"(p));
    return a;
}
__device__ __forceinline__ void cp16(uint32_t dst, const void* src) {
    asm volatile("cp.async.cg.shared.global [%0], [%1], 16;" :: "r"(dst), "l"(src));
}
#define CP_COMMIT() asm volatile("cp.async.commit_group;" ::: "memory")
#define CP_WAIT(n)  asm volatile("cp.async.wait_group %0;" :: "n"(n) : "memory")

#define LDSM_X4(r0, r1, r2, r3, addr)                                          \
    asm volatile("ldmatrix.sync.aligned.m8n8.x4.shared.b16 {%0,%1,%2,%3}, [%4];" \
        : "=r"(r0), "=r"(r1), "=r"(r2), "=r"(r3) : "r"(addr))

__device__ __forceinline__ void mma_f16(
    float c[4], unsigned a0, unsigned a1, unsigned a2, unsigned a3,
    unsigned b0, unsigned b1)
{
    asm volatile(
        "mma.sync.aligned.m16n8k16.row.col.f32.f16.f16.f32 "
        "{%0,%1,%2,%3},{%4,%5,%6,%7},{%8,%9},{%0,%1,%2,%3};"
        : "+f"(c[0]), "+f"(c[1]), "+f"(c[2]), "+f"(c[3])
        : "r"(a0), "r"(a1), "r"(a2), "r"(a3), "r"(b0), "r"(b1));
}
__device__ __forceinline__ unsigned pack_h2(float lo, float hi) {
    __half2 h = __floats2half2_rn(lo, hi);
    return *(unsigned*)&h;
}

// ---------------------------------------------------------------------------
// Split fp32 -> (hi fp16, lo fp16 * 1024)
// ---------------------------------------------------------------------------
__global__ void __launch_bounds__(256) split_fp16(
    const float* __restrict__ x, __half* __restrict__ hi,
    __half* __restrict__ lo, int n4)
{
    int i = blockIdx.x * 256 + threadIdx.x;
    if (i >= n4) return;
    float4 v = ((const float4*)x)[i];
    __half h0 = __float2half_rn(v.x);
    __half h1 = __float2half_rn(v.y);
    __half h2 = __float2half_rn(v.z);
    __half h3 = __float2half_rn(v.w);
    __half2* hp = (__half2*)(hi + 4 * (size_t)i);
    hp[0] = __halves2half2(h0, h1);
    hp[1] = __halves2half2(h2, h3);
    __half2* lp = (__half2*)(lo + 4 * (size_t)i);
    lp[0] = __floats2half2_rn((v.x - __half2float(h0)) * SPLIT_SC,
                              (v.y - __half2float(h1)) * SPLIT_SC);
    lp[1] = __floats2half2_rn((v.z - __half2float(h2)) * SPLIT_SC,
                              (v.w - __half2float(h3)) * SPLIT_SC);
}

// ---------------------------------------------------------------------------
// Split-fp16 GEMM v2 (NT): C = A*B^T + bias.
// BM=128, BN=64, BK=32; 256 thr = 8 warps (4m x 2n), warp tile 32x32.
// 3-stage cp.async pipeline; ldmatrix.x4 fragment loads; 2 CTAs/SM.
// smem stage (halves, stride 40): Ah 0 | Al 5120 | Bh 10240 | Bl 12800.
// ---------------------------------------------------------------------------
#define GST 40
#define STG_H 15360
#define AOFF_L 5120
#define BOFF_H 10240
#define BOFF_L 12800
#define NSTAGE 3
#define GEMM_SMEM_B (NSTAGE * STG_H * 2)   // 92160 bytes

__global__ void __launch_bounds__(256, 2) gemm_split_v2(
    const __half* __restrict__ Ah, const __half* __restrict__ Al,
    const __half* __restrict__ Bh, const __half* __restrict__ Bl,
    const float* __restrict__ bias, float* __restrict__ C,
    int M, int N, int K)
{
    extern __shared__ __half sg[];
    const uint32_t sbase = smem_u32(sg);

    const int t      = threadIdx.x;
    const int lane   = t & 31;
    const int warp   = t >> 5;
    const int warp_m = warp >> 1;
    const int warp_n = warp & 1;
    const int g      = lane >> 2;
    const int tg     = lane & 3;

    const int m0 = blockIdx.y * 128;
    const int n0 = blockIdx.x * 64;

#define LOAD_STAGE(stg, k0)                                                    \
    {                                                                          \
        uint32_t bb = sbase + (stg) * (STG_H * 2);                             \
        _Pragma("unroll")                                                      \
        for (int i = 0; i < 2; i++) {                                          \
            int id = t + i * 256;                                              \
            int r = id >> 2, c = (id & 3) * 8;                                 \
            uint32_t d = bb + (r * GST + c) * 2;                               \
            size_t s = (size_t)(m0 + r) * K + (k0) + c;                        \
            cp16(d, Ah + s);                                                   \
            cp16(d + AOFF_L * 2, Al + s);                                      \
        }                                                                      \
        {                                                                      \
            int r = t >> 2, c = (t & 3) * 8;                                   \
            uint32_t d = bb + (BOFF_H + r * GST + c) * 2;                      \
            size_t s = (size_t)(n0 + r) * K + (k0) + c;                        \
            cp16(d, Bh + s);                                                   \
            cp16(d + (BOFF_L - BOFF_H) * 2, Bl + s);                           \
        }                                                                      \
        CP_COMMIT();                                                           \
    }

    float accm[2][4][4], accc[2][4][4];
#pragma unroll
    for (int mi = 0; mi < 2; mi++)
#pragma unroll
        for (int nb = 0; nb < 4; nb++)
#pragma unroll
            for (int i = 0; i < 4; i++) { accm[mi][nb][i] = 0.0f; accc[mi][nb][i] = 0.0f; }

    const int nch = K >> 5;   // 32 for K=1024
    LOAD_STAGE(0, 0);
    LOAD_STAGE(1, 32);
    LOAD_STAGE(2, 64);

    // ldmatrix lane addressing (within a stage, halves)
    const int a_row = warp_m * 32 + (lane & 15);
    const int a_hc  = (lane >> 4) * 8;
    const int b_row = warp_n * 32 + ((lane >> 4) << 3) + (lane & 7);
    const int b_hc  = ((lane >> 3) & 1) * 8;

    int stg = 0;
    for (int it = 0; it < nch; it++) {
        CP_WAIT(NSTAGE - 1);
        __syncthreads();

        uint32_t bb = sbase + stg * (STG_H * 2);
#pragma unroll
        for (int ks = 0; ks < 2; ks++) {
            unsigned ah[2][4], al[2][4], bh[2][4], bl[2][4];
#pragma unroll
            for (int mi = 0; mi < 2; mi++) {
                uint32_t a = bb + ((a_row + mi * 16) * GST + ks * 16 + a_hc) * 2;
                LDSM_X4(ah[mi][0], ah[mi][1], ah[mi][2], ah[mi][3], a);
                LDSM_X4(al[mi][0], al[mi][1], al[mi][2], al[mi][3], a + AOFF_L * 2);
            }
#pragma unroll
            for (int p = 0; p < 2; p++) {
                uint32_t b = bb + (BOFF_H + (b_row + p * 16) * GST + ks * 16 + b_hc) * 2;
                LDSM_X4(bh[p][0], bh[p][1], bh[p][2], bh[p][3], b);
                LDSM_X4(bl[p][0], bl[p][1], bl[p][2], bl[p][3], b + (BOFF_L - BOFF_H) * 2);
            }
#pragma unroll
            for (int p = 0; p < 2; p++)
#pragma unroll
                for (int q = 0; q < 2; q++) {
                    int nb = 2 * p + q;
#pragma unroll
                    for (int mi = 0; mi < 2; mi++) {
                        mma_f16(accm[mi][nb], ah[mi][0], ah[mi][1], ah[mi][2], ah[mi][3],
                                bh[p][2 * q], bh[p][2 * q + 1]);
                        mma_f16(accc[mi][nb], ah[mi][0], ah[mi][1], ah[mi][2], ah[mi][3],
                                bl[p][2 * q], bl[p][2 * q + 1]);
                        mma_f16(accc[mi][nb], al[mi][0], al[mi][1], al[mi][2], al[mi][3],
                                bh[p][2 * q], bh[p][2 * q + 1]);
                    }
                }
        }
        __syncthreads();

        if (it + NSTAGE < nch) {
            LOAD_STAGE(stg, (it + NSTAGE) * 32);
        } else {
            CP_COMMIT();
        }
        stg = (stg == 2) ? 0 : stg + 1;
    }

    // ---- Epilogue ----
#pragma unroll
    for (int mi = 0; mi < 2; mi++) {
        int row = m0 + warp_m * 32 + mi * 16 + g;
#pragma unroll
        for (int nb = 0; nb < 4; nb++) {
            int n = n0 + warp_n * 32 + nb * 8 + 2 * tg;
            float b0 = bias[n], b1 = bias[n + 1];
            float2 v;
            v.x = accm[mi][nb][0] + accc[mi][nb][0] * SPLIT_INV + b0;
            v.y = accm[mi][nb][1] + accc[mi][nb][1] * SPLIT_INV + b1;
            *(float2*)&C[(size_t)row * N + n] = v;
            v.x = accm[mi][nb][2] + accc[mi][nb][2] * SPLIT_INV + b0;
            v.y = accm[mi][nb][3] + accc[mi][nb][3] * SPLIT_INV + b1;
            *(float2*)&C[(size_t)(row + 8) * N + n] = v;
        }
    }
#undef LOAD_STAGE
}

// ---------------------------------------------------------------------------
// Prep 1: RoPE + scale(q) + fp16 convert for q,k.
// ---------------------------------------------------------------------------
__global__ void __launch_bounds__(256) prep_qk(
    const float* __restrict__ qkv, const float* __restrict__ cosT,
    const float* __restrict__ sinT, __half* __restrict__ qk)
{
    int idx = blockIdx.x * 256 + threadIdx.x;
    int d   = idx & 31;
    int h   = (idx >> 5) & 15;
    int tok = idx >> 9;

    const float* src = qkv + (size_t)tok * (3 * DMODEL) + h * DHEAD;
    float c1 = cosT[tok * DHEAD + d];
    float s1 = sinT[tok * DHEAD + d];
    float c2 = cosT[tok * DHEAD + d + 32];
    float s2 = sinT[tok * DHEAD + d + 32];

    float q1 = src[d], q2 = src[d + 32];
    __half* dq = qk + (size_t)tok * (2 * DMODEL) + h * DHEAD;
    dq[d]      = __float2half((q1 * c1 - q2 * s1) * 0.125f);
    dq[d + 32] = __float2half((q2 * c2 + q1 * s2) * 0.125f);

    float k1 = src[DMODEL + d], k2 = src[DMODEL + d + 32];
    __half* dk = dq + DMODEL;
    dk[d]      = __float2half(k1 * c1 - k2 * s1);
    dk[d + 32] = __float2half(k2 * c2 + k1 * s2);
}

// ---------------------------------------------------------------------------
// Prep 2: transpose V per head into [sg][h][d][tok], fp16.
// ---------------------------------------------------------------------------
__global__ void __launch_bounds__(256) prep_vt(
    const float* __restrict__ qkv, __half* __restrict__ vt)
{
    __shared__ float tile[64][65];
    const int tc = blockIdx.x;
    const int h  = blockIdx.y;
    const int t  = threadIdx.x;

#pragma unroll
    for (int i = 0; i < 4; i++) {
        int f  = t + i * 256;
        int r  = f >> 4;
        int c4 = (f & 15) * 4;
        float4 v = *(const float4*)(qkv + (size_t)(tc * 64 + r) * (3 * DMODEL)
                                    + 2 * DMODEL + h * DHEAD + c4);
        tile[r][c4 + 0] = v.x; tile[r][c4 + 1] = v.y;
        tile[r][c4 + 2] = v.z; tile[r][c4 + 3] = v.w;
    }
    __syncthreads();

    const int sg  = (tc * 64) / SEG;
    const int tin = (tc * 64) % SEG;
#pragma unroll
    for (int i = 0; i < 4; i++) {
        int f  = t + i * 256;
        int d  = f >> 4;
        int t4 = (f & 15) * 4;
        __half2 a = __floats2half2_rn(tile[t4 + 0][d], tile[t4 + 1][d]);
        __half2 b = __floats2half2_rn(tile[t4 + 2][d], tile[t4 + 3][d]);
        __half2* dst = (__half2*)(vt + ((size_t)(sg * NHEAD + h) * DHEAD + d) * SEG
                                  + tin + t4);
        dst[0] = a;
        dst[1] = b;
    }
}

// ---------------------------------------------------------------------------
// fp16 tensor-core flash attention (proven; unchanged).
// ---------------------------------------------------------------------------
#define HST 72
#define KTILE_H (64 * HST)

__global__ void __launch_bounds__(256, 2) attn_f16_kernel(
    const __half* __restrict__ qk, const __half* __restrict__ vt,
    __half* __restrict__ oh, __half* __restrict__ ol)
{
    __shared__ __half sm[4 * KTILE_H];
    __half* Qs = sm;

    const int mt = blockIdx.x;
    const int h  = blockIdx.y;
    const int sg = blockIdx.z;

    const int t    = threadIdx.x;
    const int lane = t & 31;
    const int warp = t >> 5;
    const int g    = lane >> 2;
    const int tg   = lane & 3;

    const __half* kbase = qk + DMODEL + h * DHEAD;
    const __half* vbase = vt + (size_t)(sg * NHEAD + h) * DHEAD * SEG;

#pragma unroll
    for (int i = 0; i < 4; i++) {
        int f  = t + i * 256;
        int r  = f >> 3;
        int c8 = (f & 7) * 8;
        int tok = sg * SEG + mt * 128 + r;
        uint4 v = *(const uint4*)(qk + (size_t)tok * (2 * DMODEL) + h * DHEAD + c8);
        *(uint4*)&Qs[r * HST + c8] = v;
    }
    __syncthreads();

    uint4 rk[2], rv[2];
    {
        const int r  = t >> 3;
        const int c8 = (t & 7) * 8;
        rk[0] = *(const uint4*)(kbase + (size_t)(sg * SEG + r) * (2 * DMODEL) + c8);
        rk[1] = *(const uint4*)(kbase + (size_t)(sg * SEG + r + 32) * (2 * DMODEL) + c8);
        rv[0] = *(const uint4*)(vbase + (size_t)r * SEG + c8);
        rv[1] = *(const uint4*)(vbase + (size_t)(r + 32) * SEG + c8);
    }

    unsigned qa[4][4];
    {
        int row = warp * 16 + g;
#pragma unroll
        for (int ks = 0; ks < 4; ks++) {
            int c = ks * 16 + 2 * tg;
            qa[ks][0] = *(const unsigned*)&Qs[row * HST + c];
            qa[ks][1] = *(const unsigned*)&Qs[(row + 8) * HST + c];
            qa[ks][2] = *(const unsigned*)&Qs[row * HST + c + 8];
            qa[ks][3] = *(const unsigned*)&Qs[(row + 8) * HST + c + 8];
        }
    }
    __syncthreads();

    {
        const int r  = t >> 3;
        const int c8 = (t & 7) * 8;
        *(uint4*)&sm[0 * KTILE_H + r * HST + c8]        = rk[0];
        *(uint4*)&sm[0 * KTILE_H + (r + 32) * HST + c8] = rk[1];
        *(uint4*)&sm[2 * KTILE_H + r * HST + c8]        = rv[0];
        *(uint4*)&sm[2 * KTILE_H + (r + 32) * HST + c8] = rv[1];
    }
    __syncthreads();

    float acc[8][4];
#pragma unroll
    for (int nb = 0; nb < 8; nb++)
#pragma unroll
        for (int i = 0; i < 4; i++) acc[nb][i] = 0.0f;
    float m_lo = -INFINITY, m_hi = -INFINITY, l_lo = 0.0f, l_hi = 0.0f;

    for (int jt = 0; jt < 16; jt++) {
        if (jt < 15) {
            const int r  = t >> 3;
            const int c8 = (t & 7) * 8;
            int j0n = (jt + 1) * 64;
            rk[0] = *(const uint4*)(kbase + (size_t)(sg * SEG + j0n + r) * (2 * DMODEL) + c8);
            rk[1] = *(const uint4*)(kbase + (size_t)(sg * SEG + j0n + r + 32) * (2 * DMODEL) + c8);
            rv[0] = *(const uint4*)(vbase + (size_t)r * SEG + j0n + c8);
            rv[1] = *(const uint4*)(vbase + (size_t)(r + 32) * SEG + j0n + c8);
        }

        const __half* Kst = sm + (jt & 1) * KTILE_H;
        const __half* Vst = sm + 2 * KTILE_H + (jt & 1) * KTILE_H;

        float sf[8][4];
#pragma unroll
        for (int nb = 0; nb < 8; nb++) {
            sf[nb][0] = sf[nb][1] = sf[nb][2] = sf[nb][3] = 0.0f;
            const __half* kp = &Kst[(nb * 8 + g) * HST];
#pragma unroll
            for (int ks = 0; ks < 4; ks++) {
                unsigned b0 = *(const unsigned*)&kp[ks * 16 + 2 * tg];
                unsigned b1 = *(const unsigned*)&kp[ks * 16 + 2 * tg + 8];
                mma_f16(sf[nb], qa[ks][0], qa[ks][1], qa[ks][2], qa[ks][3], b0, b1);
            }
        }

        float tmax_lo = -INFINITY, tmax_hi = -INFINITY;
#pragma unroll
        for (int nb = 0; nb < 8; nb++) {
            tmax_lo = fmaxf(tmax_lo, fmaxf(sf[nb][0], sf[nb][1]));
            tmax_hi = fmaxf(tmax_hi, fmaxf(sf[nb][2], sf[nb][3]));
        }
        tmax_lo = fmaxf(tmax_lo, __shfl_xor_sync(0xffffffffu, tmax_lo, 1));
        tmax_lo = fmaxf(tmax_lo, __shfl_xor_sync(0xffffffffu, tmax_lo, 2));
        tmax_hi = fmaxf(tmax_hi, __shfl_xor_sync(0xffffffffu, tmax_hi, 1));
        tmax_hi = fmaxf(tmax_hi, __shfl_xor_sync(0xffffffffu, tmax_hi, 2));

        float mn_lo = fmaxf(m_lo, tmax_lo);
        float mn_hi = fmaxf(m_hi, tmax_hi);
        float fac_lo = __expf(m_lo - mn_lo);
        float fac_hi = __expf(m_hi - mn_hi);
        m_lo = mn_lo; m_hi = mn_hi;

        float rs_lo = 0.0f, rs_hi = 0.0f;
#pragma unroll
        for (int nb = 0; nb < 8; nb++) {
            sf[nb][0] = __expf(sf[nb][0] - m_lo);
            sf[nb][1] = __expf(sf[nb][1] - m_lo);
            sf[nb][2] = __expf(sf[nb][2] - m_hi);
            sf[nb][3] = __expf(sf[nb][3] - m_hi);
            rs_lo += sf[nb][0] + sf[nb][1];
            rs_hi += sf[nb][2] + sf[nb][3];
        }
        rs_lo += __shfl_xor_sync(0xffffffffu, rs_lo, 1);
        rs_lo += __shfl_xor_sync(0xffffffffu, rs_lo, 2);
        rs_hi += __shfl_xor_sync(0xffffffffu, rs_hi, 1);
        rs_hi += __shfl_xor_sync(0xffffffffu, rs_hi, 2);

        l_lo = l_lo * fac_lo + rs_lo;
        l_hi = l_hi * fac_hi + rs_hi;
#pragma unroll
        for (int nb = 0; nb < 8; nb++) {
            acc[nb][0] *= fac_lo; acc[nb][1] *= fac_lo;
            acc[nb][2] *= fac_hi; acc[nb][3] *= fac_hi;
        }

#pragma unroll
        for (int kc = 0; kc < 4; kc++) {
            unsigned pa0 = pack_h2(sf[2 * kc][0],     sf[2 * kc][1]);
            unsigned pa1 = pack_h2(sf[2 * kc][2],     sf[2 * kc][3]);
            unsigned pa2 = pack_h2(sf[2 * kc + 1][0], sf[2 * kc + 1][1]);
            unsigned pa3 = pack_h2(sf[2 * kc + 1][2], sf[2 * kc + 1][3]);
#pragma unroll
            for (int nb = 0; nb < 8; nb++) {
                const __half* vp = &Vst[(nb * 8 + g) * HST + kc * 16];
                unsigned vb0 = *(const unsigned*)&vp[2 * tg];
                unsigned vb1 = *(const unsigned*)&vp[2 * tg + 8];
                mma_f16(acc[nb], pa0, pa1, pa2, pa3, vb0, vb1);
            }
        }

        if (jt < 15) {
            __half* Kd = sm + ((jt + 1) & 1) * KTILE_H;
            __half* Vd = sm + 2 * KTILE_H + ((jt + 1) & 1) * KTILE_H;
            const int r  = t >> 3;
            const int c8 = (t & 7) * 8;
            *(uint4*)&Kd[r * HST + c8]        = rk[0];
            *(uint4*)&Kd[(r + 32) * HST + c8] = rk[1];
            *(uint4*)&Vd[r * HST + c8]        = rv[0];
            *(uint4*)&Vd[(r + 32) * HST + c8] = rv[1];
        }
        __syncthreads();
    }

    float inv_lo = 1.0f / l_lo;
    float inv_hi = 1.0f / l_hi;
    int tok_lo = sg * SEG + mt * 128 + warp * 16 + g;
#pragma unroll
    for (int nb = 0; nb < 8; nb++) {
        int col = h * DHEAD + nb * 8 + tg * 2;
        {
            float v0 = acc[nb][0] * inv_lo, v1 = acc[nb][1] * inv_lo;
            __half h0 = __float2half_rn(v0), h1 = __float2half_rn(v1);
            *(__half2*)&oh[(size_t)tok_lo * DMODEL + col] = __halves2half2(h0, h1);
            *(__half2*)&ol[(size_t)tok_lo * DMODEL + col] =
                __floats2half2_rn((v0 - __half2float(h0)) * SPLIT_SC,
                                  (v1 - __half2float(h1)) * SPLIT_SC);
        }
        {
            float v0 = acc[nb][2] * inv_hi, v1 = acc[nb][3] * inv_hi;
            __half h0 = __float2half_rn(v0), h1 = __float2half_rn(v1);
            *(__half2*)&oh[(size_t)(tok_lo + 8) * DMODEL + col] = __halves2half2(h0, h1);
            *(__half2*)&ol[(size_t)(tok_lo + 8) * DMODEL + col] =
                __floats2half2_rn((v0 - __half2float(h0)) * SPLIT_SC,
                                  (v1 - __half2float(h1)) * SPLIT_SC);
        }
    }
}

// ---------------------------------------------------------------------------
// Launch
// ---------------------------------------------------------------------------
extern "C" void kernel_launch(void* const* d_in, const int* in_sizes, int n_in,
                              void* d_out, int out_size)
{
    const float* hs     = (const float*)d_in[0];
    const float* cosT   = (const float*)d_in[1];
    const float* sinT   = (const float*)d_in[2];
    const float* qkv_w  = (const float*)d_in[3];
    const float* qkv_b  = (const float*)d_in[4];
    const float* proj_w = (const float*)d_in[5];
    const float* proj_b = (const float*)d_in[6];
    float* out = (float*)d_out;

    void *qkvp_v, *qkh_v, *vt_v, *ah_v, *al_v, *wh_v, *wl_v, *ph_v, *pl_v;
    cudaGetSymbolAddress(&qkvp_v, g_qkv);
    cudaGetSymbolAddress(&qkh_v, g_qk_h);
    cudaGetSymbolAddress(&vt_v, g_vt);
    cudaGetSymbolAddress(&ah_v, g_ah);
    cudaGetSymbolAddress(&al_v, g_al);
    cudaGetSymbolAddress(&wh_v, g_wh);
    cudaGetSymbolAddress(&wl_v, g_wl);
    cudaGetSymbolAddress(&ph_v, g_ph);
    cudaGetSymbolAddress(&pl_v, g_pl);
    float*  qkvp = (float*)qkvp_v;
    __half* qkh  = (__half*)qkh_v;
    __half* vtp  = (__half*)vt_v;
    __half* ahp  = (__half*)ah_v;
    __half* alp  = (__half*)al_v;
    __half* whp  = (__half*)wh_v;
    __half* wlp  = (__half*)wl_v;
    __half* php  = (__half*)ph_v;
    __half* plp  = (__half*)pl_v;

    cudaFuncSetAttribute(gemm_split_v2,
                         cudaFuncAttributeMaxDynamicSharedMemorySize, GEMM_SMEM_B);

    // 0) Splits
    split_fp16<<<(S_LEN * DMODEL / 4) / 256, 256>>>(hs, ahp, alp, S_LEN * DMODEL / 4);
    split_fp16<<<(3 * DMODEL * DMODEL / 4) / 256, 256>>>(qkv_w, whp, wlp, 3 * DMODEL * DMODEL / 4);
    split_fp16<<<(DMODEL * DMODEL / 4) / 256, 256>>>(proj_w, php, plp, DMODEL * DMODEL / 4);

    // 1) QKV GEMM (split fp16 tensor cores, cp.async pipeline)
    {
        dim3 grid(3 * DMODEL / 64, S_LEN / 128);
        gemm_split_v2<<<grid, 256, GEMM_SMEM_B>>>(
            ahp, alp, whp, wlp, qkv_b, qkvp, S_LEN, 3 * DMODEL, DMODEL);
    }

    // 2) Prep: RoPE+fp16 q/k, fp16 transposed v
    prep_qk<<<(S_LEN * NHEAD * 32) / 256, 256>>>(qkvp, cosT, sinT, qkh);
    {
        dim3 gv(S_LEN / 64, NHEAD);
        prep_vt<<<gv, 256>>>(qkvp, vtp);
    }

    // 3) Attention -> split-fp16 proj input
    {
        dim3 grid(SEG / 128, NHEAD, NSEG);
        attn_f16_kernel<<<grid, 256>>>(qkh, vtp, ahp, alp);
    }

    // 4) Output projection
    {
        dim3 grid(DMODEL / 64, S_LEN / 128);
        gemm_split_v2<<<grid, 256, GEMM_SMEM_B>>>(
            ahp, alp, php, plp, proj_b, out, S_LEN, DMODEL, DMODEL);
    }
}

// round 8
// speedup vs baseline: 4.6930x; 1.3552x over previous
#include <cuda_runtime.h>
#include <cuda_fp16.h>
#include <cstdint>
#include <math.h>

// Problem constants
#define S_LEN 8192
#define DMODEL 1024
#define NHEAD 16
#define DHEAD 64
#define NSEG 8
#define SEG 1024

#define SPLIT_SC 1024.0f
#define SPLIT_INV (1.0f / 1024.0f)

// Scratch (device globals)
__device__ float  g_qkv[S_LEN * 3 * DMODEL];
__device__ __half g_qk_h[S_LEN * 2 * DMODEL];
__device__ __half g_vt[NSEG * NHEAD * DHEAD * SEG];
__device__ __half g_ah[S_LEN * DMODEL];              // A hi (hs, then attn out)
__device__ __half g_wh[3 * DMODEL * DMODEL];
__device__ __half g_wl[3 * DMODEL * DMODEL];
__device__ __half g_ph[DMODEL * DMODEL];
__device__ __half g_pl[DMODEL * DMODEL];

// ---------------------------------------------------------------------------
// helpers
// ---------------------------------------------------------------------------
__device__ __forceinline__ uint32_t smem_u32(const void* p) {
    uint32_t a;
    asm("{ .reg .u64 tmp; cvta.to.shared.u64 tmp, %1; cvt.u32.u64 %0, tmp; }"
        : "=r"(a) : "l"(p));
    return a;
}
__device__ __forceinline__ void cp16(uint32_t dst, const void* src) {
    asm volatile("cp.async.cg.shared.global [%0], [%1], 16;" :: "r"(dst), "l"(src));
}
#define CP_COMMIT() asm volatile("cp.async.commit_group;" ::: "memory")
#define CP_WAIT(n)  asm volatile("cp.async.wait_group %0;" :: "n"(n) : "memory")

#define LDSM_X4(r0, r1, r2, r3, addr)                                          \
    asm volatile("ldmatrix.sync.aligned.m8n8.x4.shared.b16 {%0,%1,%2,%3}, [%4];" \
        : "=r"(r0), "=r"(r1), "=r"(r2), "=r"(r3) : "r"(addr))

__device__ __forceinline__ void mma_f16(
    float c[4], unsigned a0, unsigned a1, unsigned a2, unsigned a3,
    unsigned b0, unsigned b1)
{
    asm volatile(
        "mma.sync.aligned.m16n8k16.row.col.f32.f16.f16.f32 "
        "{%0,%1,%2,%3},{%4,%5,%6,%7},{%8,%9},{%0,%1,%2,%3};"
        : "+f"(c[0]), "+f"(c[1]), "+f"(c[2]), "+f"(c[3])
        : "r"(a0), "r"(a1), "r"(a2), "r"(a3), "r"(b0), "r"(b1));
}
__device__ __forceinline__ unsigned pack_h2(float lo, float hi) {
    __half2 h = __floats2half2_rn(lo, hi);
    return *(unsigned*)&h;
}

// ---------------------------------------------------------------------------
// Split fp32 -> (hi fp16, lo fp16 * 1024)  [weights]
// ---------------------------------------------------------------------------
__global__ void __launch_bounds__(256) split_fp16(
    const float* __restrict__ x, __half* __restrict__ hi,
    __half* __restrict__ lo, int n4)
{
    int i = blockIdx.x * 256 + threadIdx.x;
    if (i >= n4) return;
    float4 v = ((const float4*)x)[i];
    __half h0 = __float2half_rn(v.x);
    __half h1 = __float2half_rn(v.y);
    __half h2 = __float2half_rn(v.z);
    __half h3 = __float2half_rn(v.w);
    __half2* hp = (__half2*)(hi + 4 * (size_t)i);
    hp[0] = __halves2half2(h0, h1);
    hp[1] = __halves2half2(h2, h3);
    __half2* lp = (__half2*)(lo + 4 * (size_t)i);
    lp[0] = __floats2half2_rn((v.x - __half2float(h0)) * SPLIT_SC,
                              (v.y - __half2float(h1)) * SPLIT_SC);
    lp[1] = __floats2half2_rn((v.z - __half2float(h2)) * SPLIT_SC,
                              (v.w - __half2float(h3)) * SPLIT_SC);
}

// Convert fp32 -> fp16 (hi only) [activations]
__global__ void __launch_bounds__(256) conv_hi(
    const float* __restrict__ x, __half* __restrict__ hi, int n4)
{
    int i = blockIdx.x * 256 + threadIdx.x;
    if (i >= n4) return;
    float4 v = ((const float4*)x)[i];
    __half2* hp = (__half2*)(hi + 4 * (size_t)i);
    hp[0] = __floats2half2_rn(v.x, v.y);
    hp[1] = __floats2half2_rn(v.z, v.w);
}

// ---------------------------------------------------------------------------
// Split-fp16 GEMM v3 (NT): C = Ah*(Bh + Bl*2^-10)^T + bias.
// BM=128, BN=64, BK=32; 8 warps (4m x 2n), warp tile 32x32.
// 3-stage cp.async, SINGLE __syncthreads per iter; 2 CTAs/SM.
// smem stage (halves, stride 40): Ah 0 | Bh 5120 | Bl 7680. 20480 B/stage.
// ---------------------------------------------------------------------------
#define GST 40
#define STG_H 10240
#define BOFF_H 5120
#define BOFF_L 7680
#define NSTAGE 3
#define GEMM_SMEM_B (NSTAGE * STG_H * 2)   // 61440 bytes

__global__ void __launch_bounds__(256, 2) gemm_split_v3(
    const __half* __restrict__ Ah,
    const __half* __restrict__ Bh, const __half* __restrict__ Bl,
    const float* __restrict__ bias, float* __restrict__ C,
    int M, int N, int K)
{
    extern __shared__ __half sg[];
    const uint32_t sbase = smem_u32(sg);

    const int t      = threadIdx.x;
    const int lane   = t & 31;
    const int warp   = t >> 5;
    const int warp_m = warp >> 1;
    const int warp_n = warp & 1;
    const int g      = lane >> 2;
    const int tg     = lane & 3;

    const int m0 = blockIdx.y * 128;
    const int n0 = blockIdx.x * 64;

#define LOAD_STAGE(stg, k0)                                                    \
    {                                                                          \
        uint32_t bb = sbase + (stg) * (STG_H * 2);                             \
        _Pragma("unroll")                                                      \
        for (int i = 0; i < 2; i++) {                                          \
            int id = t + i * 256;                                              \
            int r = id >> 2, c = (id & 3) * 8;                                 \
            cp16(bb + (r * GST + c) * 2, Ah + (size_t)(m0 + r) * K + (k0) + c);\
        }                                                                      \
        {                                                                      \
            int r = t >> 2, c = (t & 3) * 8;                                   \
            uint32_t d = bb + (BOFF_H + r * GST + c) * 2;                      \
            size_t s = (size_t)(n0 + r) * K + (k0) + c;                        \
            cp16(d, Bh + s);                                                   \
            cp16(d + (BOFF_L - BOFF_H) * 2, Bl + s);                           \
        }                                                                      \
        CP_COMMIT();                                                           \
    }

    float accm[2][4][4], accc[2][4][4];
#pragma unroll
    for (int mi = 0; mi < 2; mi++)
#pragma unroll
        for (int nb = 0; nb < 4; nb++)
#pragma unroll
            for (int i = 0; i < 4; i++) { accm[mi][nb][i] = 0.0f; accc[mi][nb][i] = 0.0f; }

    const int nch = K >> 5;
    LOAD_STAGE(0, 0);
    LOAD_STAGE(1, 32);

    const int a_row = warp_m * 32 + (lane & 15);
    const int a_hc  = (lane >> 4) * 8;
    const int b_row = warp_n * 32 + ((lane >> 4) << 3) + (lane & 7);
    const int b_hc  = ((lane >> 3) & 1) * 8;

    for (int it = 0; it < nch; it++) {
        CP_WAIT(1);
        __syncthreads();
        // prefetch chunk it+2 into the buffer all warps released last iter
        if (it + 2 < nch) {
            LOAD_STAGE((it + 2) % NSTAGE, (it + 2) * 32);
        } else {
            CP_COMMIT();
        }

        uint32_t bb = sbase + (it % NSTAGE) * (STG_H * 2);
#pragma unroll
        for (int ks = 0; ks < 2; ks++) {
            unsigned ah[2][4], bh[2][4], bl[2][4];
#pragma unroll
            for (int mi = 0; mi < 2; mi++) {
                uint32_t a = bb + ((a_row + mi * 16) * GST + ks * 16 + a_hc) * 2;
                LDSM_X4(ah[mi][0], ah[mi][1], ah[mi][2], ah[mi][3], a);
            }
#pragma unroll
            for (int p = 0; p < 2; p++) {
                uint32_t b = bb + (BOFF_H + (b_row + p * 16) * GST + ks * 16 + b_hc) * 2;
                LDSM_X4(bh[p][0], bh[p][1], bh[p][2], bh[p][3], b);
                LDSM_X4(bl[p][0], bl[p][1], bl[p][2], bl[p][3], b + (BOFF_L - BOFF_H) * 2);
            }
#pragma unroll
            for (int p = 0; p < 2; p++)
#pragma unroll
                for (int q = 0; q < 2; q++) {
                    int nb = 2 * p + q;
#pragma unroll
                    for (int mi = 0; mi < 2; mi++) {
                        mma_f16(accm[mi][nb], ah[mi][0], ah[mi][1], ah[mi][2], ah[mi][3],
                                bh[p][2 * q], bh[p][2 * q + 1]);
                        mma_f16(accc[mi][nb], ah[mi][0], ah[mi][1], ah[mi][2], ah[mi][3],
                                bl[p][2 * q], bl[p][2 * q + 1]);
                    }
                }
        }
    }

    // ---- Epilogue ----
#pragma unroll
    for (int mi = 0; mi < 2; mi++) {
        int row = m0 + warp_m * 32 + mi * 16 + g;
#pragma unroll
        for (int nb = 0; nb < 4; nb++) {
            int n = n0 + warp_n * 32 + nb * 8 + 2 * tg;
            float b0 = bias[n], b1 = bias[n + 1];
            float2 v;
            v.x = accm[mi][nb][0] + accc[mi][nb][0] * SPLIT_INV + b0;
            v.y = accm[mi][nb][1] + accc[mi][nb][1] * SPLIT_INV + b1;
            *(float2*)&C[(size_t)row * N + n] = v;
            v.x = accm[mi][nb][2] + accc[mi][nb][2] * SPLIT_INV + b0;
            v.y = accm[mi][nb][3] + accc[mi][nb][3] * SPLIT_INV + b1;
            *(float2*)&C[(size_t)(row + 8) * N + n] = v;
        }
    }
#undef LOAD_STAGE
}

// ---------------------------------------------------------------------------
// Prep 1: RoPE + scale(q) + fp16 convert for q,k.
// ---------------------------------------------------------------------------
__global__ void __launch_bounds__(256) prep_qk(
    const float* __restrict__ qkv, const float* __restrict__ cosT,
    const float* __restrict__ sinT, __half* __restrict__ qk)
{
    int idx = blockIdx.x * 256 + threadIdx.x;
    int d   = idx & 31;
    int h   = (idx >> 5) & 15;
    int tok = idx >> 9;

    const float* src = qkv + (size_t)tok * (3 * DMODEL) + h * DHEAD;
    float c1 = cosT[tok * DHEAD + d];
    float s1 = sinT[tok * DHEAD + d];
    float c2 = cosT[tok * DHEAD + d + 32];
    float s2 = sinT[tok * DHEAD + d + 32];

    float q1 = src[d], q2 = src[d + 32];
    __half* dq = qk + (size_t)tok * (2 * DMODEL) + h * DHEAD;
    dq[d]      = __float2half((q1 * c1 - q2 * s1) * 0.125f);
    dq[d + 32] = __float2half((q2 * c2 + q1 * s2) * 0.125f);

    float k1 = src[DMODEL + d], k2 = src[DMODEL + d + 32];
    __half* dk = dq + DMODEL;
    dk[d]      = __float2half(k1 * c1 - k2 * s1);
    dk[d + 32] = __float2half(k2 * c2 + k1 * s2);
}

// ---------------------------------------------------------------------------
// Prep 2: transpose V per head into [sg][h][d][tok], fp16.
// ---------------------------------------------------------------------------
__global__ void __launch_bounds__(256) prep_vt(
    const float* __restrict__ qkv, __half* __restrict__ vt)
{
    __shared__ float tile[64][65];
    const int tc = blockIdx.x;
    const int h  = blockIdx.y;
    const int t  = threadIdx.x;

#pragma unroll
    for (int i = 0; i < 4; i++) {
        int f  = t + i * 256;
        int r  = f >> 4;
        int c4 = (f & 15) * 4;
        float4 v = *(const float4*)(qkv + (size_t)(tc * 64 + r) * (3 * DMODEL)
                                    + 2 * DMODEL + h * DHEAD + c4);
        tile[r][c4 + 0] = v.x; tile[r][c4 + 1] = v.y;
        tile[r][c4 + 2] = v.z; tile[r][c4 + 3] = v.w;
    }
    __syncthreads();

    const int sg  = (tc * 64) / SEG;
    const int tin = (tc * 64) % SEG;
#pragma unroll
    for (int i = 0; i < 4; i++) {
        int f  = t + i * 256;
        int d  = f >> 4;
        int t4 = (f & 15) * 4;
        __half2 a = __floats2half2_rn(tile[t4 + 0][d], tile[t4 + 1][d]);
        __half2 b = __floats2half2_rn(tile[t4 + 2][d], tile[t4 + 3][d]);
        __half2* dst = (__half2*)(vt + ((size_t)(sg * NHEAD + h) * DHEAD + d) * SEG
                                  + tin + t4);
        dst[0] = a;
        dst[1] = b;
    }
}

// ---------------------------------------------------------------------------
// fp16 tensor-core flash attention; epilogue emits fp16 hi only.
// ---------------------------------------------------------------------------
#define HST 72
#define KTILE_H (64 * HST)

__global__ void __launch_bounds__(256, 2) attn_f16_kernel(
    const __half* __restrict__ qk, const __half* __restrict__ vt,
    __half* __restrict__ oh)
{
    __shared__ __half sm[4 * KTILE_H];
    __half* Qs = sm;

    const int mt = blockIdx.x;
    const int h  = blockIdx.y;
    const int sg = blockIdx.z;

    const int t    = threadIdx.x;
    const int lane = t & 31;
    const int warp = t >> 5;
    const int g    = lane >> 2;
    const int tg   = lane & 3;

    const __half* kbase = qk + DMODEL + h * DHEAD;
    const __half* vbase = vt + (size_t)(sg * NHEAD + h) * DHEAD * SEG;

#pragma unroll
    for (int i = 0; i < 4; i++) {
        int f  = t + i * 256;
        int r  = f >> 3;
        int c8 = (f & 7) * 8;
        int tok = sg * SEG + mt * 128 + r;
        uint4 v = *(const uint4*)(qk + (size_t)tok * (2 * DMODEL) + h * DHEAD + c8);
        *(uint4*)&Qs[r * HST + c8] = v;
    }
    __syncthreads();

    uint4 rk[2], rv[2];
    {
        const int r  = t >> 3;
        const int c8 = (t & 7) * 8;
        rk[0] = *(const uint4*)(kbase + (size_t)(sg * SEG + r) * (2 * DMODEL) + c8);
        rk[1] = *(const uint4*)(kbase + (size_t)(sg * SEG + r + 32) * (2 * DMODEL) + c8);
        rv[0] = *(const uint4*)(vbase + (size_t)r * SEG + c8);
        rv[1] = *(const uint4*)(vbase + (size_t)(r + 32) * SEG + c8);
    }

    unsigned qa[4][4];
    {
        int row = warp * 16 + g;
#pragma unroll
        for (int ks = 0; ks < 4; ks++) {
            int c = ks * 16 + 2 * tg;
            qa[ks][0] = *(const unsigned*)&Qs[row * HST + c];
            qa[ks][1] = *(const unsigned*)&Qs[(row + 8) * HST + c];
            qa[ks][2] = *(const unsigned*)&Qs[row * HST + c + 8];
            qa[ks][3] = *(const unsigned*)&Qs[(row + 8) * HST + c + 8];
        }
    }
    __syncthreads();

    {
        const int r  = t >> 3;
        const int c8 = (t & 7) * 8;
        *(uint4*)&sm[0 * KTILE_H + r * HST + c8]        = rk[0];
        *(uint4*)&sm[0 * KTILE_H + (r + 32) * HST + c8] = rk[1];
        *(uint4*)&sm[2 * KTILE_H + r * HST + c8]        = rv[0];
        *(uint4*)&sm[2 * KTILE_H + (r + 32) * HST + c8] = rv[1];
    }
    __syncthreads();

    float acc[8][4];
#pragma unroll
    for (int nb = 0; nb < 8; nb++)
#pragma unroll
        for (int i = 0; i < 4; i++) acc[nb][i] = 0.0f;
    float m_lo = -INFINITY, m_hi = -INFINITY, l_lo = 0.0f, l_hi = 0.0f;

    for (int jt = 0; jt < 16; jt++) {
        if (jt < 15) {
            const int r  = t >> 3;
            const int c8 = (t & 7) * 8;
            int j0n = (jt + 1) * 64;
            rk[0] = *(const uint4*)(kbase + (size_t)(sg * SEG + j0n + r) * (2 * DMODEL) + c8);
            rk[1] = *(const uint4*)(kbase + (size_t)(sg * SEG + j0n + r + 32) * (2 * DMODEL) + c8);
            rv[0] = *(const uint4*)(vbase + (size_t)r * SEG + j0n + c8);
            rv[1] = *(const uint4*)(vbase + (size_t)(r + 32) * SEG + j0n + c8);
        }

        const __half* Kst = sm + (jt & 1) * KTILE_H;
        const __half* Vst = sm + 2 * KTILE_H + (jt & 1) * KTILE_H;

        float sf[8][4];
#pragma unroll
        for (int nb = 0; nb < 8; nb++) {
            sf[nb][0] = sf[nb][1] = sf[nb][2] = sf[nb][3] = 0.0f;
            const __half* kp = &Kst[(nb * 8 + g) * HST];
#pragma unroll
            for (int ks = 0; ks < 4; ks++) {
                unsigned b0 = *(const unsigned*)&kp[ks * 16 + 2 * tg];
                unsigned b1 = *(const unsigned*)&kp[ks * 16 + 2 * tg + 8];
                mma_f16(sf[nb], qa[ks][0], qa[ks][1], qa[ks][2], qa[ks][3], b0, b1);
            }
        }

        float tmax_lo = -INFINITY, tmax_hi = -INFINITY;
#pragma unroll
        for (int nb = 0; nb < 8; nb++) {
            tmax_lo = fmaxf(tmax_lo, fmaxf(sf[nb][0], sf[nb][1]));
            tmax_hi = fmaxf(tmax_hi, fmaxf(sf[nb][2], sf[nb][3]));
        }
        tmax_lo = fmaxf(tmax_lo, __shfl_xor_sync(0xffffffffu, tmax_lo, 1));
        tmax_lo = fmaxf(tmax_lo, __shfl_xor_sync(0xffffffffu, tmax_lo, 2));
        tmax_hi = fmaxf(tmax_hi, __shfl_xor_sync(0xffffffffu, tmax_hi, 1));
        tmax_hi = fmaxf(tmax_hi, __shfl_xor_sync(0xffffffffu, tmax_hi, 2));

        float mn_lo = fmaxf(m_lo, tmax_lo);
        float mn_hi = fmaxf(m_hi, tmax_hi);
        float fac_lo = __expf(m_lo - mn_lo);
        float fac_hi = __expf(m_hi - mn_hi);
        m_lo = mn_lo; m_hi = mn_hi;

        float rs_lo = 0.0f, rs_hi = 0.0f;
#pragma unroll
        for (int nb = 0; nb < 8; nb++) {
            sf[nb][0] = __expf(sf[nb][0] - m_lo);
            sf[nb][1] = __expf(sf[nb][1] - m_lo);
            sf[nb][2] = __expf(sf[nb][2] - m_hi);
            sf[nb][3] = __expf(sf[nb][3] - m_hi);
            rs_lo += sf[nb][0] + sf[nb][1];
            rs_hi += sf[nb][2] + sf[nb][3];
        }
        rs_lo += __shfl_xor_sync(0xffffffffu, rs_lo, 1);
        rs_lo += __shfl_xor_sync(0xffffffffu, rs_lo, 2);
        rs_hi += __shfl_xor_sync(0xffffffffu, rs_hi, 1);
        rs_hi += __shfl_xor_sync(0xffffffffu, rs_hi, 2);

        l_lo = l_lo * fac_lo + rs_lo;
        l_hi = l_hi * fac_hi + rs_hi;
#pragma unroll
        for (int nb = 0; nb < 8; nb++) {
            acc[nb][0] *= fac_lo; acc[nb][1] *= fac_lo;
            acc[nb][2] *= fac_hi; acc[nb][3] *= fac_hi;
        }

#pragma unroll
        for (int kc = 0; kc < 4; kc++) {
            unsigned pa0 = pack_h2(sf[2 * kc][0],     sf[2 * kc][1]);
            unsigned pa1 = pack_h2(sf[2 * kc][2],     sf[2 * kc][3]);
            unsigned pa2 = pack_h2(sf[2 * kc + 1][0], sf[2 * kc + 1][1]);
            unsigned pa3 = pack_h2(sf[2 * kc + 1][2], sf[2 * kc + 1][3]);
#pragma unroll
            for (int nb = 0; nb < 8; nb++) {
                const __half* vp = &Vst[(nb * 8 + g) * HST + kc * 16];
                unsigned vb0 = *(const unsigned*)&vp[2 * tg];
                unsigned vb1 = *(const unsigned*)&vp[2 * tg + 8];
                mma_f16(acc[nb], pa0, pa1, pa2, pa3, vb0, vb1);
            }
        }

        if (jt < 15) {
            __half* Kd = sm + ((jt + 1) & 1) * KTILE_H;
            __half* Vd = sm + 2 * KTILE_H + ((jt + 1) & 1) * KTILE_H;
            const int r  = t >> 3;
            const int c8 = (t & 7) * 8;
            *(uint4*)&Kd[r * HST + c8]        = rk[0];
            *(uint4*)&Kd[(r + 32) * HST + c8] = rk[1];
            *(uint4*)&Vd[r * HST + c8]        = rv[0];
            *(uint4*)&Vd[(r + 32) * HST + c8] = rv[1];
        }
        __syncthreads();
    }

    float inv_lo = 1.0f / l_lo;
    float inv_hi = 1.0f / l_hi;
    int tok_lo = sg * SEG + mt * 128 + warp * 16 + g;
#pragma unroll
    for (int nb = 0; nb < 8; nb++) {
        int col = h * DHEAD + nb * 8 + tg * 2;
        *(__half2*)&oh[(size_t)tok_lo * DMODEL + col] =
            __floats2half2_rn(acc[nb][0] * inv_lo, acc[nb][1] * inv_lo);
        *(__half2*)&oh[(size_t)(tok_lo + 8) * DMODEL + col] =
            __floats2half2_rn(acc[nb][2] * inv_hi, acc[nb][3] * inv_hi);
    }
}

// ---------------------------------------------------------------------------
// Launch
// ---------------------------------------------------------------------------
extern "C" void kernel_launch(void* const* d_in, const int* in_sizes, int n_in,
                              void* d_out, int out_size)
{
    const float* hs     = (const float*)d_in[0];
    const float* cosT   = (const float*)d_in[1];
    const float* sinT   = (const float*)d_in[2];
    const float* qkv_w  = (const float*)d_in[3];
    const float* qkv_b  = (const float*)d_in[4];
    const float* proj_w = (const float*)d_in[5];
    const float* proj_b = (const float*)d_in[6];
    float* out = (float*)d_out;

    void *qkvp_v, *qkh_v, *vt_v, *ah_v, *wh_v, *wl_v, *ph_v, *pl_v;
    cudaGetSymbolAddress(&qkvp_v, g_qkv);
    cudaGetSymbolAddress(&qkh_v, g_qk_h);
    cudaGetSymbolAddress(&vt_v, g_vt);
    cudaGetSymbolAddress(&ah_v, g_ah);
    cudaGetSymbolAddress(&wh_v, g_wh);
    cudaGetSymbolAddress(&wl_v, g_wl);
    cudaGetSymbolAddress(&ph_v, g_ph);
    cudaGetSymbolAddress(&pl_v, g_pl);
    float*  qkvp = (float*)qkvp_v;
    __half* qkh  = (__half*)qkh_v;
    __half* vtp  = (__half*)vt_v;
    __half* ahp  = (__half*)ah_v;
    __half* whp  = (__half*)wh_v;
    __half* wlp  = (__half*)wl_v;
    __half* php  = (__half*)ph_v;
    __half* plp  = (__half*)pl_v;

    cudaFuncSetAttribute(gemm_split_v3,
                         cudaFuncAttributeMaxDynamicSharedMemorySize, GEMM_SMEM_B);

    // 0) Splits / converts
    conv_hi<<<(S_LEN * DMODEL / 4) / 256, 256>>>(hs, ahp, S_LEN * DMODEL / 4);
    split_fp16<<<(3 * DMODEL * DMODEL / 4) / 256, 256>>>(qkv_w, whp, wlp, 3 * DMODEL * DMODEL / 4);
    split_fp16<<<(DMODEL * DMODEL / 4) / 256, 256>>>(proj_w, php, plp, DMODEL * DMODEL / 4);

    // 1) QKV GEMM
    {
        dim3 grid(3 * DMODEL / 64, S_LEN / 128);
        gemm_split_v3<<<grid, 256, GEMM_SMEM_B>>>(
            ahp, whp, wlp, qkv_b, qkvp, S_LEN, 3 * DMODEL, DMODEL);
    }

    // 2) Prep: RoPE+fp16 q/k, fp16 transposed v
    prep_qk<<<(S_LEN * NHEAD * 32) / 256, 256>>>(qkvp, cosT, sinT, qkh);
    {
        dim3 gv(S_LEN / 64, NHEAD);
        prep_vt<<<gv, 256>>>(qkvp, vtp);
    }

    // 3) Attention -> fp16 proj input
    {
        dim3 grid(SEG / 128, NHEAD, NSEG);
        attn_f16_kernel<<<grid, 256>>>(qkh, vtp, ahp);
    }

    // 4) Output projection
    {
        dim3 grid(DMODEL / 64, S_LEN / 128);
        gemm_split_v3<<<grid, 256, GEMM_SMEM_B>>>(
            ahp, php, plp, proj_b, out, S_LEN, DMODEL, DMODEL);
    }
}